// round 13
// baseline (speedup 1.0000x reference)
#include <cuda_runtime.h>
#include <cuda_bf16.h>
#include <math.h>
#include <stdint.h>

// Problem constants
#define BB 8
#define TT 96
#define NN 20000
#define PP 12
#define LL 3
#define DD 32
#define CC 128
#define MM 64
#define NBLK 157              // ceil(NN/128) row-blocks per batch
#define NCH 100               // node chunks for ksum partials
#define CHSZ (NN/NCH)         // 200

#define SFAC 0.4204482076268573f   // 32^{-1/4}
#define RATIO 0.125f               // 1/sqrt(64)
#define EPSRF 1e-6f

typedef unsigned long long ull;

// ---- packed fp32x2 helpers ----
__device__ __forceinline__ ull splat2(float v){
    ull r; asm("mov.b64 %0, {%1, %1};" : "=l"(r) : "f"(v)); return r;
}
__device__ __forceinline__ void fma2(ull& acc, ull a, ull b){
    asm("fma.rn.f32x2 %0, %1, %2, %0;" : "+l"(acc) : "l"(a), "l"(b));
}
__device__ __forceinline__ float2 unpack2(ull v){
    float2 f; asm("mov.b64 {%0, %1}, %2;" : "=f"(f.x), "=f"(f.y) : "l"(v)); return f;
}

// ---- HMMA helper: base-ISA bf16 mma (compiles for compute_103) ----
__device__ __forceinline__ void mma_bf16(float d[4], const uint32_t a[4], const uint32_t b[2]){
    asm volatile("mma.sync.aligned.m16n8k16.row.col.f32.bf16.bf16.f32 "
        "{%0,%1,%2,%3}, {%4,%5,%6,%7}, {%8,%9}, {%0,%1,%2,%3};"
        : "+f"(d[0]), "+f"(d[1]), "+f"(d[2]), "+f"(d[3])
        : "r"(a[0]), "r"(a[1]), "r"(a[2]), "r"(a[3]), "r"(b[0]), "r"(b[1]));
}
__device__ __forceinline__ uint32_t packbf(float a, float b){
    __nv_bfloat162 h = __floats2bfloat162_rn(a, b);
    uint32_t r; memcpy(&r, &h, 4); return r;
}
__device__ __forceinline__ uint32_t lds_u32(const char* base, int elem){   // elem in bf16 units
    return *(const uint32_t*)(base + elem*2);
}

// ---------------- device scratch ----------
__device__ float g_h   [(size_t)BB*NN*CC];
__device__ float g_skip[(size_t)BB*NN*CC];
__device__ float g_phiq[(size_t)BB*NN*MM];
__device__ float g_phik[(size_t)BB*NN*MM];
__device__ float g_A1[NN*DD];
__device__ float g_A2[NN*DD];
__device__ float g_c1[BB*DD];
__device__ float g_c2[BB*DD];
__device__ float g_Pc2[BB*MM];
__device__ float g_mark[BB*DD];
__device__ float g_tvv[BB*DD];
__device__ float g_wvv[BB*DD];
__device__ float g_colmax[MM];
__device__ float g_stabk[BB];
__device__ float g_kvpart[(size_t)BB*NBLK*MM*CC];
__device__ float g_kv[BB*MM*CC];
__device__ float g_kspart[BB*NCH*MM];
__device__ float g_ksum[BB*MM];
__device__ float g_den[BB*NN];

// ---------------- per-batch constants -----------------
__global__ void k_const(const float* __restrict__ xmark,
                        const float* __restrict__ time_tab,
                        const float* __restrict__ week_tab,
                        const float* __restrict__ input_w,
                        const float* __restrict__ input_b,
                        const float* __restrict__ w1_w, const float* __restrict__ w1_b,
                        const float* __restrict__ w2_w, const float* __restrict__ w2_b,
                        const float* __restrict__ proj)
{
    int b = blockIdx.x, t = threadIdx.x;
    __shared__ float xm0[TT], xm1[TT], stv[DD], swv[DD], sc1[DD], sc2[DD];

    float m0 = xmark[(b*TT + (TT-1))*2 + 0];
    float m1 = xmark[(b*TT + (TT-1))*2 + 1];
    int tod = (int)(m0 * (float)TT); tod = min(max(tod, 0), TT-1);
    int dow = (int)(m1 * 7.0f);      dow = min(max(dow, 0), 6);

    if (t < TT) { xm0[t] = xmark[(b*TT+t)*2]; xm1[t] = xmark[(b*TT+t)*2+1]; }
    if (t < DD) {
        float tv = time_tab[tod*DD+t], wv = week_tab[dow*DD+t];
        stv[t] = tv; swv[t] = wv;
        g_tvv[b*DD+t] = tv; g_wvv[b*DD+t] = wv;
    }
    __syncthreads();
    if (t < DD) {
        float mc = input_b[t];
        for (int k = 0; k < TT; k++)
            mc += xm0[k]*input_w[t*(3*TT)+TT+k] + xm1[k]*input_w[t*(3*TT)+2*TT+k];
        g_mark[b*DD+t] = mc;
        float v1 = w1_b[t], v2 = w2_b[t];
        for (int g = 0; g < DD; g++) {
            v1 += stv[g]*w1_w[t*(3*DD)+DD+g] + swv[g]*w1_w[t*(3*DD)+2*DD+g];
            v2 += stv[g]*w2_w[t*(3*DD)+DD+g] + swv[g]*w2_w[t*(3*DD)+2*DD+g];
        }
        v1 *= 2.0f; v2 *= 2.0f;
        sc1[t] = v1; sc2[t] = v2;
        g_c1[b*DD+t] = v1; g_c2[b*DD+t] = v2;
    }
    __syncthreads();
    if (t < MM) {
        float p = 0.f;
        #pragma unroll
        for (int c = 0; c < DD; c++) p += sc2[c]*proj[t*DD+c];
        g_Pc2[b*MM+t] = SFAC * p;
    }
}

__global__ void k_node(const float* __restrict__ node_emb,
                       const float* __restrict__ w1_w,
                       const float* __restrict__ w2_w)
{
    __shared__ float w1s[DD*DD], w2s[DD*DD];
    int t = threadIdx.x;
    for (int i = t; i < DD*DD; i += 256) {
        int c = i / DD, g = i % DD;
        w1s[i] = w1_w[c*(3*DD)+g];
        w2s[i] = w2_w[c*(3*DD)+g];
    }
    __syncthreads();
    int n = blockIdx.x*256 + t;
    if (n >= NN) return;
    float ne[DD];
    #pragma unroll
    for (int g = 0; g < DD; g++) ne[g] = node_emb[n*DD+g];
    #pragma unroll 4
    for (int c = 0; c < DD; c++) {
        float a1 = 0.f, a2 = 0.f;
        #pragma unroll
        for (int g = 0; g < DD; g++) { a1 += ne[g]*w1s[c*DD+g]; a2 += ne[g]*w2s[c*DD+g]; }
        g_A1[n*DD+c] = 2.0f*a1;
        g_A2[n*DD+c] = 2.0f*a2;
    }
}

__global__ void k_colmax(const float* __restrict__ proj)
{
    int m = blockIdx.x, t = threadIdx.x;
    __shared__ float pr[DD];
    __shared__ float red[8];
    if (t < DD) pr[t] = proj[m*DD+t];
    __syncthreads();
    float mx = -1e30f;
    for (int n = t; n < NN; n += 256) {
        float d = 0.f;
        #pragma unroll
        for (int c = 0; c < DD; c++) d += g_A2[n*DD+c]*pr[c];
        mx = fmaxf(mx, d);
    }
    for (int o = 16; o; o >>= 1) mx = fmaxf(mx, __shfl_down_sync(0xffffffffu, mx, o));
    if ((t & 31) == 0) red[t >> 5] = mx;
    __syncthreads();
    if (t == 0) {
        float r = red[0];
        for (int w = 1; w < 8; w++) r = fmaxf(r, red[w]);
        g_colmax[m] = SFAC * r;
    }
}

__global__ void k_stab()
{
    int b = blockIdx.x, t = threadIdx.x;
    __shared__ float red[2];
    float v = g_colmax[t] + g_Pc2[b*MM+t];
    for (int o = 16; o; o >>= 1) v = fmaxf(v, __shfl_down_sync(0xffffffffu, v, o));
    if ((t & 31) == 0) red[t >> 5] = v;
    __syncthreads();
    if (t == 0) g_stabk[b] = fmaxf(red[0], red[1]);
}

__global__ __launch_bounds__(128) void k_phi(const float* __restrict__ proj)
{
    int b = blockIdx.y, t = threadIdx.x;
    __shared__ float psT[DD*MM];
    __shared__ float c1s[DD], c2s[DD];
    for (int i = t; i < DD*MM; i += 128) {
        int m = i >> 5, c = i & 31;
        psT[c*MM+m] = proj[m*DD+c];
    }
    if (t < DD) { c1s[t] = g_c1[b*DD+t]; c2s[t] = g_c2[b*DD+t]; }
    __syncthreads();
    int n = blockIdx.x*128 + t;
    if (n >= NN) return;

    size_t base = ((size_t)(b*NN) + n) * MM;
    ull dd[32];
    float nv[DD];

    float sq = 0.f;
    #pragma unroll
    for (int c = 0; c < DD; c++) { float v = SFAC*(g_A1[n*DD+c] + c1s[c]); nv[c] = v; sq += v*v; }
    float diag = 0.5f*sq;
    #pragma unroll
    for (int i = 0; i < 32; i++) dd[i] = 0ull;
    #pragma unroll 4
    for (int c = 0; c < DD; c++) {
        ull s = splat2(nv[c]);
        const ulonglong2* pp = (const ulonglong2*)&psT[c*MM];
        #pragma unroll
        for (int i = 0; i < 16; i++) {
            ulonglong2 pv = pp[i];
            fma2(dd[2*i],   s, pv.x);
            fma2(dd[2*i+1], s, pv.y);
        }
    }
    float mx = -1e30f;
    #pragma unroll
    for (int i = 0; i < 32; i++) { float2 f = unpack2(dd[i]); mx = fmaxf(mx, fmaxf(f.x, f.y)); }
    float off = diag + mx;
    #pragma unroll
    for (int i = 0; i < 16; i++) {
        float2 a = unpack2(dd[2*i]), c2 = unpack2(dd[2*i+1]);
        float4 o;
        o.x = RATIO*(__expf(a.x  - off) + EPSRF);
        o.y = RATIO*(__expf(a.y  - off) + EPSRF);
        o.z = RATIO*(__expf(c2.x - off) + EPSRF);
        o.w = RATIO*(__expf(c2.y - off) + EPSRF);
        *(float4*)&g_phiq[base + 4*i] = o;
    }

    sq = 0.f;
    #pragma unroll
    for (int c = 0; c < DD; c++) { float v = SFAC*(g_A2[n*DD+c] + c2s[c]); nv[c] = v; sq += v*v; }
    diag = 0.5f*sq;
    #pragma unroll
    for (int i = 0; i < 32; i++) dd[i] = 0ull;
    #pragma unroll 4
    for (int c = 0; c < DD; c++) {
        ull s = splat2(nv[c]);
        const ulonglong2* pp = (const ulonglong2*)&psT[c*MM];
        #pragma unroll
        for (int i = 0; i < 16; i++) {
            ulonglong2 pv = pp[i];
            fma2(dd[2*i],   s, pv.x);
            fma2(dd[2*i+1], s, pv.y);
        }
    }
    off = diag + g_stabk[b];
    #pragma unroll
    for (int i = 0; i < 16; i++) {
        float2 a = unpack2(dd[2*i]), c2 = unpack2(dd[2*i+1]);
        float4 o;
        o.x = RATIO*(__expf(a.x  - off) + EPSRF);
        o.y = RATIO*(__expf(a.y  - off) + EPSRF);
        o.z = RATIO*(__expf(c2.x - off) + EPSRF);
        o.w = RATIO*(__expf(c2.y - off) + EPSRF);
        *(float4*)&g_phik[base + 4*i] = o;
    }
}

__global__ void k_input(const float* __restrict__ x,
                        const float* __restrict__ input_w,
                        const float* __restrict__ node_emb)
{
    int b = blockIdx.y, t = threadIdx.x;
    __shared__ float wts[TT*DD];
    __shared__ float mk[DD], tv[DD], wv[DD];
    for (int i = t; i < TT*DD; i += 128) {
        int tt = i / DD, c = i % DD;
        wts[i] = input_w[c*(3*TT)+tt];
    }
    if (t < DD) { mk[t] = g_mark[b*DD+t]; tv[t] = g_tvv[b*DD+t]; wv[t] = g_wvv[b*DD+t]; }
    __syncthreads();
    int n = blockIdx.x*128 + t;
    if (n >= NN) return;
    float acc[DD];
    #pragma unroll
    for (int c = 0; c < DD; c++) acc[c] = mk[c];
    for (int tt = 0; tt < TT; tt++) {
        float xv = x[((size_t)b*TT + tt)*NN + n];
        #pragma unroll
        for (int c = 0; c < DD; c++) acc[c] += xv * wts[tt*DD+c];
    }
    size_t base = ((size_t)(b*NN) + n) * CC;
    #pragma unroll
    for (int i = 0; i < 8; i++) {
        float4 v = make_float4(acc[4*i], acc[4*i+1], acc[4*i+2], acc[4*i+3]);
        *(float4*)&g_h[base + 4*i] = v; *(float4*)&g_skip[base + 4*i] = v;
    }
    #pragma unroll
    for (int i = 0; i < 8; i++) {
        float4 v = *(const float4*)&node_emb[n*DD + 4*i];
        *(float4*)&g_h[base + DD + 4*i] = v; *(float4*)&g_skip[base + DD + 4*i] = v;
    }
    #pragma unroll
    for (int i = 0; i < 8; i++) {
        float4 v = make_float4(tv[4*i], tv[4*i+1], tv[4*i+2], tv[4*i+3]);
        *(float4*)&g_h[base + 2*DD + 4*i] = v; *(float4*)&g_skip[base + 2*DD + 4*i] = v;
    }
    #pragma unroll
    for (int i = 0; i < 8; i++) {
        float4 v = make_float4(wv[4*i], wv[4*i+1], wv[4*i+2], wv[4*i+3]);
        *(float4*)&g_h[base + 3*DD + 4*i] = v; *(float4*)&g_skip[base + 3*DD + 4*i] = v;
    }
}

__global__ void k_ksum()
{
    int ch = blockIdx.x, b = blockIdx.y, t = threadIdx.x;
    int m = t & 63, sub = t >> 6;
    int n0 = ch*CHSZ;
    float acc = 0.f;
    for (int n = n0 + sub; n < n0 + CHSZ; n += 4)
        acc += g_phik[((size_t)(b*NN) + n)*MM + m];
    __shared__ float red[256];
    red[t] = acc;
    __syncthreads();
    if (t < 64)
        g_kspart[(b*NCH+ch)*MM + m] = red[m] + red[64+m] + red[128+m] + red[192+m];
}

__global__ void k_ksumred()
{
    int b = blockIdx.x, m = threadIdx.x;
    float s = 0.f;
    for (int ch = 0; ch < NCH; ch++) s += g_kspart[(b*NCH+ch)*MM + m];
    g_ksum[b*MM+m] = s;
}

__global__ void k_den()
{
    int b = blockIdx.y, t = threadIdx.x;
    __shared__ float ks[MM];
    if (t < MM) ks[t] = g_ksum[b*MM+t];
    __syncthreads();
    int n = blockIdx.x*128 + t;
    if (n >= NN) return;
    size_t base = ((size_t)(b*NN) + n)*MM;
    float d = 0.f;
    #pragma unroll
    for (int m = 0; m < MM; m++) d += g_phiq[base+m]*ks[m];
    g_den[b*NN+n] = d;
}

// ---------------- fused gate (bf16-split HMMA) + kv-partial ------------------
#define STR   136                       // bf16 elems per row
#define TSZ   (128*STR*2)               // 34816 B per tile
#define SMEM_GATE (6*TSZ)               // 208896 B
#define USTRIDE 132

__device__ __forceinline__ void split_store(char* hiP, char* loP, float4 a, float4 c){
    float av[8] = {a.x,a.y,a.z,a.w,c.x,c.y,c.z,c.w};
    float l[8];
    #pragma unroll
    for (int j = 0; j < 8; j++) {
        float hb = __bfloat162float(__float2bfloat16(av[j]));
        l[j] = av[j] - hb;
    }
    uint4 hi, lo;
    hi.x = packbf(av[0],av[1]); hi.y = packbf(av[2],av[3]);
    hi.z = packbf(av[4],av[5]); hi.w = packbf(av[6],av[7]);
    lo.x = packbf(l[0],l[1]);   lo.y = packbf(l[2],l[3]);
    lo.z = packbf(l[4],l[5]);   lo.w = packbf(l[6],l[7]);
    *(uint4*)hiP = hi;
    *(uint4*)loP = lo;
}

__global__ __launch_bounds__(512)
void k_gatekv(const float* __restrict__ in_w,
              const float* __restrict__ in_b,
              const float* __restrict__ out_w,
              const float* __restrict__ out_b,
              int layer)
{
    extern __shared__ __align__(16) char smem[];
    char* AH = smem;
    char* AL = smem + TSZ;
    char* IH = smem + 2*TSZ;
    char* IL = smem + 3*TSZ;
    char* OH = smem + 4*TSZ;
    char* OL = smem + 5*TSZ;

    int t = threadIdx.x;
    int wid = t >> 5, lid = t & 31;
    int lane4 = lid >> 2, lanem = lid & 3;
    int blk = blockIdx.x, b = blockIdx.y;
    int n0 = blk*128;
    size_t batchBase = (size_t)b*NN;
    const float* IW = in_w  + (size_t)layer*CC*CC;
    const float* OW = out_w + (size_t)layer*CC*CC;

    #pragma unroll
    for (int it = 0; it < 4; it++) {
        int lin = t + it*512;
        int row = lin >> 4, seg = lin & 15;
        int c8 = seg*8;
        int boff = row*(STR*2) + c8*2;
        int nrow = min(n0 + row, NN-1);
        float4 a = *(const float4*)&g_h[(batchBase + nrow)*CC + c8];
        float4 c = *(const float4*)&g_h[(batchBase + nrow)*CC + c8 + 4];
        split_store(AH + boff, AL + boff, a, c);
        a = *(const float4*)&IW[(size_t)row*CC + c8];
        c = *(const float4*)&IW[(size_t)row*CC + c8 + 4];
        split_store(IH + boff, IL + boff, a, c);
        a = *(const float4*)&OW[(size_t)row*CC + c8];
        c = *(const float4*)&OW[(size_t)row*CC + c8 + 4];
        split_store(OH + boff, OL + boff, a, c);
    }
    __syncthreads();

    int mrow = (wid & 3)*32;
    int ncol = (wid >> 2)*32;

    float di[2][4][4], dq[2][4][4];
    #pragma unroll
    for (int mt = 0; mt < 2; mt++)
        #pragma unroll
        for (int nt = 0; nt < 4; nt++)
            #pragma unroll
            for (int j = 0; j < 4; j++) { di[mt][nt][j] = 0.f; dq[mt][nt][j] = 0.f; }

    #pragma unroll
    for (int kk = 0; kk < 8; kk++) {
        int k0 = kk*16;
        uint32_t a[2][4];
        #pragma unroll
        for (int mt = 0; mt < 2; mt++) {
            int r = mrow + mt*16 + lane4;
            int cidx = k0 + lanem*2;
            a[mt][0] = lds_u32(AH, r*STR + cidx);
            a[mt][1] = lds_u32(AH, (r+8)*STR + cidx);
            a[mt][2] = lds_u32(AH, r*STR + cidx + 8);
            a[mt][3] = lds_u32(AH, (r+8)*STR + cidx + 8);
        }
        #pragma unroll
        for (int nt = 0; nt < 4; nt++) {
            int nr = ncol + nt*8 + lane4;
            int koff = k0 + lanem*2;
            uint32_t bih[2] = { lds_u32(IH, nr*STR + koff), lds_u32(IH, nr*STR + koff + 8) };
            uint32_t boh[2] = { lds_u32(OH, nr*STR + koff), lds_u32(OH, nr*STR + koff + 8) };
            uint32_t bil[2] = { lds_u32(IL, nr*STR + koff), lds_u32(IL, nr*STR + koff + 8) };
            uint32_t bol[2] = { lds_u32(OL, nr*STR + koff), lds_u32(OL, nr*STR + koff + 8) };
            mma_bf16(di[0][nt], a[0], bih); mma_bf16(di[1][nt], a[1], bih);
            mma_bf16(dq[0][nt], a[0], boh); mma_bf16(dq[1][nt], a[1], boh);
            mma_bf16(di[0][nt], a[0], bil); mma_bf16(di[1][nt], a[1], bil);
            mma_bf16(dq[0][nt], a[0], bol); mma_bf16(dq[1][nt], a[1], bol);
        }
    }
    #pragma unroll
    for (int kk = 0; kk < 8; kk++) {
        int k0 = kk*16;
        uint32_t a[2][4];
        #pragma unroll
        for (int mt = 0; mt < 2; mt++) {
            int r = mrow + mt*16 + lane4;
            int cidx = k0 + lanem*2;
            a[mt][0] = lds_u32(AL, r*STR + cidx);
            a[mt][1] = lds_u32(AL, (r+8)*STR + cidx);
            a[mt][2] = lds_u32(AL, r*STR + cidx + 8);
            a[mt][3] = lds_u32(AL, (r+8)*STR + cidx + 8);
        }
        #pragma unroll
        for (int nt = 0; nt < 4; nt++) {
            int nr = ncol + nt*8 + lane4;
            int koff = k0 + lanem*2;
            uint32_t bih[2] = { lds_u32(IH, nr*STR + koff), lds_u32(IH, nr*STR + koff + 8) };
            uint32_t boh[2] = { lds_u32(OH, nr*STR + koff), lds_u32(OH, nr*STR + koff + 8) };
            mma_bf16(di[0][nt], a[0], bih); mma_bf16(di[1][nt], a[1], bih);
            mma_bf16(dq[0][nt], a[0], boh); mma_bf16(dq[1][nt], a[1], boh);
        }
    }
    __syncthreads();

    float* U  = (float*)smem;
    float* PK = (float*)(smem + 2*TSZ);
    #pragma unroll
    for (int mt = 0; mt < 2; mt++) {
        #pragma unroll
        for (int half = 0; half < 2; half++) {
            int row = mrow + mt*16 + lane4 + half*8;
            bool ok = (n0 + row) < NN;
            #pragma unroll
            for (int nt = 0; nt < 4; nt++) {
                int col = ncol + nt*8 + lanem*2;
                float2 bi2 = *(const float2*)&in_b [layer*CC + col];
                float2 bo2 = *(const float2*)&out_b[layer*CC + col];
                float v0 = di[mt][nt][half*2+0] + bi2.x;
                float v1 = di[mt][nt][half*2+1] + bi2.y;
                float2 uv;
                uv.x = ok ? (dq[mt][nt][half*2+0]+bo2.x) / (1.f+__expf(-v0)) : 0.f;
                uv.y = ok ? (dq[mt][nt][half*2+1]+bo2.y) / (1.f+__expf(-v1)) : 0.f;
                *(float2*)&U[row*USTRIDE + col] = uv;
            }
        }
    }
    #pragma unroll
    for (int it = 0; it < 4; it++) {
        int i = t + it*512;
        int row = i >> 4, m4 = (i & 15)*4;
        int n = n0 + row;
        float4 v = make_float4(0.f,0.f,0.f,0.f);
        if (n < NN) v = *(const float4*)&g_phik[(batchBase + n)*MM + m4];
        *(float4*)&PK[row*64 + m4] = v;
    }
    __syncthreads();

    {
        int mg = t >> 5;
        int ck = t & 31;
        ull acc[4][2];
        #pragma unroll
        for (int i = 0; i < 4; i++) { acc[i][0] = 0ull; acc[i][1] = 0ull; }
        #pragma unroll 4
        for (int row = 0; row < 128; row++) {
            float4 pm = *(const float4*)&PK[row*64 + mg*4];
            ulonglong2 uc = *(const ulonglong2*)&U[row*USTRIDE + ck*4];
            ull s0 = splat2(pm.x), s1 = splat2(pm.y), s2 = splat2(pm.z), s3 = splat2(pm.w);
            fma2(acc[0][0], s0, uc.x); fma2(acc[0][1], s0, uc.y);
            fma2(acc[1][0], s1, uc.x); fma2(acc[1][1], s1, uc.y);
            fma2(acc[2][0], s2, uc.x); fma2(acc[2][1], s2, uc.y);
            fma2(acc[3][0], s3, uc.x); fma2(acc[3][1], s3, uc.y);
        }
        float* dst = &g_kvpart[((size_t)(b*NBLK) + blk)*MM*CC];
        #pragma unroll
        for (int i = 0; i < 4; i++) {
            *(ull*)&dst[(mg*4+i)*CC + ck*4]     = acc[i][0];
            *(ull*)&dst[(mg*4+i)*CC + ck*4 + 2] = acc[i][1];
        }
    }
}

__global__ void k_kvred()
{
    int b = blockIdx.y, t = threadIdx.x;       // grid (32, BB), 256 thr
    int i = blockIdx.x*256 + t;
    float s = 0.f;
    for (int blk = 0; blk < NBLK; blk++)
        s += g_kvpart[((size_t)(b*NBLK) + blk)*MM*CC + i];
    g_kv[b*MM*CC + i] = s;
}

// ---------------- num GEMM (bf16-split HMMA) + divide + residual + LN -------
// A = phiq tile [128 x 64] (row-major), B = kv^T [128 c x 64 m] (col-major n,k).
// 256 threads, 8 warps, each warp a 32x64 output tile.
#define NSTR  72                        // bf16 elems per row (64 + 8 pad)
#define TSZN  (128*NSTR*2)              // 18432 B per tile
#define SMEM_NUM (4*TSZN)               // 73728 B (stage 128x132 f32 = 67584 reuses it)
#define NSTG  132

__global__ __launch_bounds__(256) void k_num(const float* __restrict__ ln_g,
                                             const float* __restrict__ ln_b,
                                             int layer)
{
    extern __shared__ __align__(16) char nsm[];
    char* AH = nsm;
    char* AL = nsm + TSZN;
    char* BH = nsm + 2*TSZN;
    char* BL = nsm + 3*TSZN;
    int b = blockIdx.y, t = threadIdx.x;
    int wid = t >> 5, lid = t & 31;
    int lane4 = lid >> 2, lanem = lid & 3;
    int nbase = blockIdx.x*128;
    size_t batchBase = (size_t)b*NN;

    // phiq tile -> AH/AL
    #pragma unroll
    for (int it = 0; it < 8; it++) {
        int i = t + it*256;               // 0..2047
        int row = i >> 4, m4 = (i & 15)*4;
        int n = nbase + row;
        float4 v = make_float4(0.f,0.f,0.f,0.f);
        if (n < NN) v = *(const float4*)&g_phiq[(batchBase + n)*MM + m4];
        float av[4] = {v.x, v.y, v.z, v.w}, l[4];
        #pragma unroll
        for (int j = 0; j < 4; j++) {
            float hb = __bfloat162float(__float2bfloat16(av[j]));
            l[j] = av[j] - hb;
        }
        uint2 hi = make_uint2(packbf(av[0],av[1]), packbf(av[2],av[3]));
        uint2 lo = make_uint2(packbf(l[0],l[1]),   packbf(l[2],l[3]));
        int boff = (row*NSTR + m4)*2;
        *(uint2*)(AH + boff) = hi;
        *(uint2*)(AL + boff) = lo;
    }
    // kv^T -> BH/BL  (kv is 32 KB, L2-hot; strided reads OK)
    #pragma unroll
    for (int it = 0; it < 8; it++) {
        int i = t + it*256;
        int c = i >> 4, m4 = (i & 15)*4;
        float av[4], l[4];
        #pragma unroll
        for (int j = 0; j < 4; j++) av[j] = g_kv[b*MM*CC + (m4+j)*CC + c];
        #pragma unroll
        for (int j = 0; j < 4; j++) {
            float hb = __bfloat162float(__float2bfloat16(av[j]));
            l[j] = av[j] - hb;
        }
        uint2 hi = make_uint2(packbf(av[0],av[1]), packbf(av[2],av[3]));
        uint2 lo = make_uint2(packbf(l[0],l[1]),   packbf(l[2],l[3]));
        int boff = (c*NSTR + m4)*2;
        *(uint2*)(BH + boff) = hi;
        *(uint2*)(BL + boff) = lo;
    }
    __syncthreads();

    // warp tiling: 8 warps, 32 rows x 64 cols each
    int mrow = (wid & 3)*32;
    int ncol = (wid >> 2)*64;
    float d[2][8][4];
    #pragma unroll
    for (int mt = 0; mt < 2; mt++)
        #pragma unroll
        for (int nt = 0; nt < 8; nt++)
            #pragma unroll
            for (int j = 0; j < 4; j++) d[mt][nt][j] = 0.f;

    // pass 1: A_hi x (B_hi + B_lo)
    #pragma unroll
    for (int kk = 0; kk < 4; kk++) {
        int k0 = kk*16;
        uint32_t a[2][4];
        #pragma unroll
        for (int mt = 0; mt < 2; mt++) {
            int r = mrow + mt*16 + lane4;
            int cidx = k0 + lanem*2;
            a[mt][0] = lds_u32(AH, r*NSTR + cidx);
            a[mt][1] = lds_u32(AH, (r+8)*NSTR + cidx);
            a[mt][2] = lds_u32(AH, r*NSTR + cidx + 8);
            a[mt][3] = lds_u32(AH, (r+8)*NSTR + cidx + 8);
        }
        #pragma unroll
        for (int nt = 0; nt < 8; nt++) {
            int nr = ncol + nt*8 + lane4;
            int koff = k0 + lanem*2;
            uint32_t bh[2] = { lds_u32(BH, nr*NSTR + koff), lds_u32(BH, nr*NSTR + koff + 8) };
            uint32_t bl[2] = { lds_u32(BL, nr*NSTR + koff), lds_u32(BL, nr*NSTR + koff + 8) };
            mma_bf16(d[0][nt], a[0], bh); mma_bf16(d[1][nt], a[1], bh);
            mma_bf16(d[0][nt], a[0], bl); mma_bf16(d[1][nt], a[1], bl);
        }
    }
    // pass 2: A_lo x B_hi
    #pragma unroll
    for (int kk = 0; kk < 4; kk++) {
        int k0 = kk*16;
        uint32_t a[2][4];
        #pragma unroll
        for (int mt = 0; mt < 2; mt++) {
            int r = mrow + mt*16 + lane4;
            int cidx = k0 + lanem*2;
            a[mt][0] = lds_u32(AL, r*NSTR + cidx);
            a[mt][1] = lds_u32(AL, (r+8)*NSTR + cidx);
            a[mt][2] = lds_u32(AL, r*NSTR + cidx + 8);
            a[mt][3] = lds_u32(AL, (r+8)*NSTR + cidx + 8);
        }
        #pragma unroll
        for (int nt = 0; nt < 8; nt++) {
            int nr = ncol + nt*8 + lane4;
            int koff = k0 + lanem*2;
            uint32_t bh[2] = { lds_u32(BH, nr*NSTR + koff), lds_u32(BH, nr*NSTR + koff + 8) };
            mma_bf16(d[0][nt], a[0], bh); mma_bf16(d[1][nt], a[1], bh);
        }
    }
    __syncthreads();   // tiles fully read; safe to overwrite with stage

    // stage num fp32 [128][NSTG]
    float* stage = (float*)nsm;
    #pragma unroll
    for (int mt = 0; mt < 2; mt++)
        #pragma unroll
        for (int half = 0; half < 2; half++) {
            int row = mrow + mt*16 + lane4 + half*8;
            #pragma unroll
            for (int nt = 0; nt < 8; nt++) {
                int col = ncol + nt*8 + lanem*2;
                *(float2*)&stage[row*NSTG + col] =
                    make_float2(d[mt][nt][half*2+0], d[mt][nt][half*2+1]);
            }
        }
    __syncthreads();

    // LN epilogue: 8 warps x 16 rows
    for (int rr = 0; rr < 16; rr++) {
        int lrow = wid*16 + rr;
        int n = nbase + lrow;
        float4 nv4 = *(const float4*)&stage[lrow*NSTG + lid*4];
        float4 h4 = make_float4(0.f,0.f,0.f,0.f);
        float den = 1.f;
        size_t idx = (batchBase + n)*CC + lid*4;
        if (n < NN) { h4 = *(const float4*)&g_h[idx]; den = g_den[b*NN+n]; }
        float r_ = 1.0f / den;
        float v0 = nv4.x*r_ + h4.x, v1 = nv4.y*r_ + h4.y;
        float v2 = nv4.z*r_ + h4.z, v3 = nv4.w*r_ + h4.w;
        float s  = v0+v1+v2+v3;
        float s2 = v0*v0+v1*v1+v2*v2+v3*v3;
        #pragma unroll
        for (int o = 16; o; o >>= 1) {
            s  += __shfl_xor_sync(0xffffffffu, s,  o);
            s2 += __shfl_xor_sync(0xffffffffu, s2, o);
        }
        float mu  = s * (1.0f/128.0f);
        float var = s2 * (1.0f/128.0f) - mu*mu;
        float is  = rsqrtf(var + 1e-5f);
        if (n < NN) {
            float4 g4 = *(const float4*)&ln_g[layer*CC + lid*4];
            float4 b4 = *(const float4*)&ln_b[layer*CC + lid*4];
            float4 o4;
            o4.x = (v0-mu)*is*g4.x + b4.x;
            o4.y = (v1-mu)*is*g4.y + b4.y;
            o4.z = (v2-mu)*is*g4.z + b4.z;
            o4.w = (v3-mu)*is*g4.w + b4.w;
            *(float4*)&g_h[idx] = o4;
        }
    }
}

// ---------------- regression head ----------------
__global__ void k_reg(const float* __restrict__ reg_w,
                      const float* __restrict__ reg_b,
                      float* __restrict__ out)
{
    int b = blockIdx.y, t = threadIdx.x;
    __shared__ float rw[PP*2*CC];
    __shared__ float st[128*33];
    for (int i = t; i < PP*2*CC; i += 128) rw[i] = reg_w[i];
    int nbase = blockIdx.x*128;
    float acc[PP];
    #pragma unroll
    for (int p = 0; p < PP; p++) acc[p] = 0.f;
    for (int src = 0; src < 2; src++) {
        const float* S = src ? g_h : g_skip;
        for (int c0 = 0; c0 < CC; c0 += 32) {
            __syncthreads();
            #pragma unroll
            for (int k = 0; k < 32; k++) {
                int lin = t + k*128;
                int rr = lin >> 5, cc = lin & 31;
                int n = nbase + rr;
                st[rr*33+cc] = (n < NN) ? S[((size_t)(b*NN) + n)*CC + c0 + cc] : 0.f;
            }
            __syncthreads();
            #pragma unroll
            for (int cc = 0; cc < 32; cc++) {
                float v = st[t*33+cc];
                #pragma unroll
                for (int p = 0; p < PP; p++)
                    acc[p] += v * rw[p*(2*CC) + src*CC + c0 + cc];
            }
        }
    }
    int n = nbase + t;
    if (n < NN) {
        #pragma unroll
        for (int p = 0; p < PP; p++)
            out[((size_t)(b*PP) + p)*NN + n] = acc[p] + reg_b[p];
    }
}

// ---------------- launcher ----------------
extern "C" void kernel_launch(void* const* d_in, const int* in_sizes, int n_in,
                              void* d_out, int out_size)
{
    const float* x        = (const float*)d_in[0];
    const float* xmark    = (const float*)d_in[1];
    const float* node_emb = (const float*)d_in[2];
    const float* time_tab = (const float*)d_in[3];
    const float* week_tab = (const float*)d_in[4];
    const float* input_w  = (const float*)d_in[5];
    const float* input_b  = (const float*)d_in[6];
    const float* w1_w     = (const float*)d_in[7];
    const float* w1_b     = (const float*)d_in[8];
    const float* w2_w     = (const float*)d_in[9];
    const float* w2_b     = (const float*)d_in[10];
    const float* in_w     = (const float*)d_in[11];
    const float* in_b     = (const float*)d_in[12];
    const float* out_w    = (const float*)d_in[13];
    const float* out_b    = (const float*)d_in[14];
    const float* ln_g     = (const float*)d_in[15];
    const float* ln_b     = (const float*)d_in[16];
    const float* reg_w    = (const float*)d_in[17];
    const float* reg_b    = (const float*)d_in[18];
    const float* proj     = (const float*)d_in[19];
    float* out = (float*)d_out;

    cudaFuncSetAttribute(k_num,    cudaFuncAttributeMaxDynamicSharedMemorySize, SMEM_NUM);
    cudaFuncSetAttribute(k_gatekv, cudaFuncAttributeMaxDynamicSharedMemorySize, SMEM_GATE);

    dim3 gBN(NBLK, BB);

    k_const<<<BB, 128>>>(xmark, time_tab, week_tab, input_w, input_b,
                         w1_w, w1_b, w2_w, w2_b, proj);
    k_node<<<(NN + 255)/256, 256>>>(node_emb, w1_w, w2_w);
    k_colmax<<<MM, 256>>>(proj);
    k_stab<<<BB, 64>>>();
    k_phi<<<gBN, 128>>>(proj);
    k_input<<<gBN, 128>>>(x, input_w, node_emb);
    k_ksum<<<dim3(NCH, BB), 256>>>();
    k_ksumred<<<BB, 64>>>();
    k_den<<<gBN, 128>>>();

    for (int l = 0; l < LL; l++) {
        k_gatekv<<<gBN, 512, SMEM_GATE>>>(in_w, in_b, out_w, out_b, l);
        k_kvred<<<dim3(32, BB), 256>>>();
        k_num<<<gBN, 256, SMEM_NUM>>>(ln_g, ln_b, l);
    }
    k_reg<<<gBN, 128>>>(reg_w, reg_b, out);
}

// round 14
// speedup vs baseline: 1.0162x; 1.0162x over previous
#include <cuda_runtime.h>
#include <cuda_bf16.h>
#include <math.h>
#include <stdint.h>

// Problem constants
#define BB 8
#define TT 96
#define NN 20000
#define PP 12
#define LL 3
#define DD 32
#define CC 128
#define MM 64
#define NBLK 157              // ceil(NN/128) row-blocks per batch
#define NCH 100               // node chunks for ksum partials
#define CHSZ (NN/NCH)         // 200

#define SFAC 0.4204482076268573f   // 32^{-1/4}
#define RATIO 0.125f               // 1/sqrt(64)
#define EPSRF 1e-6f

typedef unsigned long long ull;

// ---- packed fp32x2 helpers ----
__device__ __forceinline__ ull splat2(float v){
    ull r; asm("mov.b64 %0, {%1, %1};" : "=l"(r) : "f"(v)); return r;
}
__device__ __forceinline__ void fma2(ull& acc, ull a, ull b){
    asm("fma.rn.f32x2 %0, %1, %2, %0;" : "+l"(acc) : "l"(a), "l"(b));
}
__device__ __forceinline__ float2 unpack2(ull v){
    float2 f; asm("mov.b64 {%0, %1}, %2;" : "=f"(f.x), "=f"(f.y) : "l"(v)); return f;
}

// ---- HMMA helper: base-ISA bf16 mma (compiles for compute_103) ----
__device__ __forceinline__ void mma_bf16(float d[4], const uint32_t a[4], const uint32_t b[2]){
    asm volatile("mma.sync.aligned.m16n8k16.row.col.f32.bf16.bf16.f32 "
        "{%0,%1,%2,%3}, {%4,%5,%6,%7}, {%8,%9}, {%0,%1,%2,%3};"
        : "+f"(d[0]), "+f"(d[1]), "+f"(d[2]), "+f"(d[3])
        : "r"(a[0]), "r"(a[1]), "r"(a[2]), "r"(a[3]), "r"(b[0]), "r"(b[1]));
}
__device__ __forceinline__ uint32_t packbf(float a, float b){
    __nv_bfloat162 h = __floats2bfloat162_rn(a, b);
    uint32_t r; memcpy(&r, &h, 4); return r;
}
__device__ __forceinline__ uint32_t lds_u32(const char* base, int elem){   // elem in bf16 units
    return *(const uint32_t*)(base + elem*2);
}

// ---------------- device scratch ----------
__device__ float g_h   [(size_t)BB*NN*CC];
__device__ float g_skip[(size_t)BB*NN*CC];
__device__ float g_phiq[(size_t)BB*NN*MM];
__device__ float g_phik[(size_t)BB*NN*MM];
__device__ float g_A1[NN*DD];
__device__ float g_A2[NN*DD];
__device__ float g_c1[BB*DD];
__device__ float g_c2[BB*DD];
__device__ float g_Pc2[BB*MM];
__device__ float g_mark[BB*DD];
__device__ float g_tvv[BB*DD];
__device__ float g_wvv[BB*DD];
__device__ float g_colmax[MM];
__device__ float g_stabk[BB];
__device__ float g_kvpart[(size_t)BB*NBLK*MM*CC];
__device__ float g_kv[BB*MM*CC];
__device__ float g_kspart[BB*NCH*MM];
__device__ float g_ksum[BB*MM];
__device__ float g_den[BB*NN];
// prebaked bf16 hi/lo weight tiles: [layer][row][c], packed 8 bf16 per uint4
__device__ uint4 g_wih[LL*CC*CC/8];
__device__ uint4 g_wil[LL*CC*CC/8];
__device__ uint4 g_woh[LL*CC*CC/8];
__device__ uint4 g_wol[LL*CC*CC/8];

// ---------------- weight prebake (bf16 hi/lo split) ----------------
__global__ void k_wprep(const float* __restrict__ in_w,
                        const float* __restrict__ out_w)
{
    int layer = blockIdx.x, t = threadIdx.x;
    const float* IW = in_w  + (size_t)layer*CC*CC;
    const float* OW = out_w + (size_t)layer*CC*CC;
    for (int i = t; i < CC*CC/8; i += 256) {
        {
            float4 a = *(const float4*)&IW[i*8];
            float4 c = *(const float4*)&IW[i*8 + 4];
            float av[8] = {a.x,a.y,a.z,a.w,c.x,c.y,c.z,c.w}, l[8];
            #pragma unroll
            for (int j = 0; j < 8; j++) {
                float hb = __bfloat162float(__float2bfloat16(av[j]));
                l[j] = av[j] - hb;
            }
            uint4 hi, lo;
            hi.x = packbf(av[0],av[1]); hi.y = packbf(av[2],av[3]);
            hi.z = packbf(av[4],av[5]); hi.w = packbf(av[6],av[7]);
            lo.x = packbf(l[0],l[1]);   lo.y = packbf(l[2],l[3]);
            lo.z = packbf(l[4],l[5]);   lo.w = packbf(l[6],l[7]);
            g_wih[layer*(CC*CC/8) + i] = hi;
            g_wil[layer*(CC*CC/8) + i] = lo;
        }
        {
            float4 a = *(const float4*)&OW[i*8];
            float4 c = *(const float4*)&OW[i*8 + 4];
            float av[8] = {a.x,a.y,a.z,a.w,c.x,c.y,c.z,c.w}, l[8];
            #pragma unroll
            for (int j = 0; j < 8; j++) {
                float hb = __bfloat162float(__float2bfloat16(av[j]));
                l[j] = av[j] - hb;
            }
            uint4 hi, lo;
            hi.x = packbf(av[0],av[1]); hi.y = packbf(av[2],av[3]);
            hi.z = packbf(av[4],av[5]); hi.w = packbf(av[6],av[7]);
            lo.x = packbf(l[0],l[1]);   lo.y = packbf(l[2],l[3]);
            lo.z = packbf(l[4],l[5]);   lo.w = packbf(l[6],l[7]);
            g_woh[layer*(CC*CC/8) + i] = hi;
            g_wol[layer*(CC*CC/8) + i] = lo;
        }
    }
}

// ---------------- per-batch constants -----------------
__global__ void k_const(const float* __restrict__ xmark,
                        const float* __restrict__ time_tab,
                        const float* __restrict__ week_tab,
                        const float* __restrict__ input_w,
                        const float* __restrict__ input_b,
                        const float* __restrict__ w1_w, const float* __restrict__ w1_b,
                        const float* __restrict__ w2_w, const float* __restrict__ w2_b,
                        const float* __restrict__ proj)
{
    int b = blockIdx.x, t = threadIdx.x;
    __shared__ float xm0[TT], xm1[TT], stv[DD], swv[DD], sc1[DD], sc2[DD];

    float m0 = xmark[(b*TT + (TT-1))*2 + 0];
    float m1 = xmark[(b*TT + (TT-1))*2 + 1];
    int tod = (int)(m0 * (float)TT); tod = min(max(tod, 0), TT-1);
    int dow = (int)(m1 * 7.0f);      dow = min(max(dow, 0), 6);

    if (t < TT) { xm0[t] = xmark[(b*TT+t)*2]; xm1[t] = xmark[(b*TT+t)*2+1]; }
    if (t < DD) {
        float tv = time_tab[tod*DD+t], wv = week_tab[dow*DD+t];
        stv[t] = tv; swv[t] = wv;
        g_tvv[b*DD+t] = tv; g_wvv[b*DD+t] = wv;
    }
    __syncthreads();
    if (t < DD) {
        float mc = input_b[t];
        for (int k = 0; k < TT; k++)
            mc += xm0[k]*input_w[t*(3*TT)+TT+k] + xm1[k]*input_w[t*(3*TT)+2*TT+k];
        g_mark[b*DD+t] = mc;
        float v1 = w1_b[t], v2 = w2_b[t];
        for (int g = 0; g < DD; g++) {
            v1 += stv[g]*w1_w[t*(3*DD)+DD+g] + swv[g]*w1_w[t*(3*DD)+2*DD+g];
            v2 += stv[g]*w2_w[t*(3*DD)+DD+g] + swv[g]*w2_w[t*(3*DD)+2*DD+g];
        }
        v1 *= 2.0f; v2 *= 2.0f;
        sc1[t] = v1; sc2[t] = v2;
        g_c1[b*DD+t] = v1; g_c2[b*DD+t] = v2;
    }
    __syncthreads();
    if (t < MM) {
        float p = 0.f;
        #pragma unroll
        for (int c = 0; c < DD; c++) p += sc2[c]*proj[t*DD+c];
        g_Pc2[b*MM+t] = SFAC * p;
    }
}

__global__ void k_node(const float* __restrict__ node_emb,
                       const float* __restrict__ w1_w,
                       const float* __restrict__ w2_w)
{
    __shared__ float w1s[DD*DD], w2s[DD*DD];
    int t = threadIdx.x;
    for (int i = t; i < DD*DD; i += 256) {
        int c = i / DD, g = i % DD;
        w1s[i] = w1_w[c*(3*DD)+g];
        w2s[i] = w2_w[c*(3*DD)+g];
    }
    __syncthreads();
    int n = blockIdx.x*256 + t;
    if (n >= NN) return;
    float ne[DD];
    #pragma unroll
    for (int g = 0; g < DD; g++) ne[g] = node_emb[n*DD+g];
    #pragma unroll 4
    for (int c = 0; c < DD; c++) {
        float a1 = 0.f, a2 = 0.f;
        #pragma unroll
        for (int g = 0; g < DD; g++) { a1 += ne[g]*w1s[c*DD+g]; a2 += ne[g]*w2s[c*DD+g]; }
        g_A1[n*DD+c] = 2.0f*a1;
        g_A2[n*DD+c] = 2.0f*a2;
    }
}

__global__ void k_colmax(const float* __restrict__ proj)
{
    int m = blockIdx.x, t = threadIdx.x;
    __shared__ float pr[DD];
    __shared__ float red[8];
    if (t < DD) pr[t] = proj[m*DD+t];
    __syncthreads();
    float mx = -1e30f;
    for (int n = t; n < NN; n += 256) {
        float d = 0.f;
        #pragma unroll
        for (int c = 0; c < DD; c++) d += g_A2[n*DD+c]*pr[c];
        mx = fmaxf(mx, d);
    }
    for (int o = 16; o; o >>= 1) mx = fmaxf(mx, __shfl_down_sync(0xffffffffu, mx, o));
    if ((t & 31) == 0) red[t >> 5] = mx;
    __syncthreads();
    if (t == 0) {
        float r = red[0];
        for (int w = 1; w < 8; w++) r = fmaxf(r, red[w]);
        g_colmax[m] = SFAC * r;
    }
}

__global__ void k_stab()
{
    int b = blockIdx.x, t = threadIdx.x;
    __shared__ float red[2];
    float v = g_colmax[t] + g_Pc2[b*MM+t];
    for (int o = 16; o; o >>= 1) v = fmaxf(v, __shfl_down_sync(0xffffffffu, v, o));
    if ((t & 31) == 0) red[t >> 5] = v;
    __syncthreads();
    if (t == 0) g_stabk[b] = fmaxf(red[0], red[1]);
}

__global__ __launch_bounds__(128) void k_phi(const float* __restrict__ proj)
{
    int b = blockIdx.y, t = threadIdx.x;
    __shared__ float psT[DD*MM];
    __shared__ float c1s[DD], c2s[DD];
    for (int i = t; i < DD*MM; i += 128) {
        int m = i >> 5, c = i & 31;
        psT[c*MM+m] = proj[m*DD+c];
    }
    if (t < DD) { c1s[t] = g_c1[b*DD+t]; c2s[t] = g_c2[b*DD+t]; }
    __syncthreads();
    int n = blockIdx.x*128 + t;
    if (n >= NN) return;

    size_t base = ((size_t)(b*NN) + n) * MM;
    ull dd[32];
    float nv[DD];

    float sq = 0.f;
    #pragma unroll
    for (int c = 0; c < DD; c++) { float v = SFAC*(g_A1[n*DD+c] + c1s[c]); nv[c] = v; sq += v*v; }
    float diag = 0.5f*sq;
    #pragma unroll
    for (int i = 0; i < 32; i++) dd[i] = 0ull;
    #pragma unroll 4
    for (int c = 0; c < DD; c++) {
        ull s = splat2(nv[c]);
        const ulonglong2* pp = (const ulonglong2*)&psT[c*MM];
        #pragma unroll
        for (int i = 0; i < 16; i++) {
            ulonglong2 pv = pp[i];
            fma2(dd[2*i],   s, pv.x);
            fma2(dd[2*i+1], s, pv.y);
        }
    }
    float mx = -1e30f;
    #pragma unroll
    for (int i = 0; i < 32; i++) { float2 f = unpack2(dd[i]); mx = fmaxf(mx, fmaxf(f.x, f.y)); }
    float off = diag + mx;
    #pragma unroll
    for (int i = 0; i < 16; i++) {
        float2 a = unpack2(dd[2*i]), c2 = unpack2(dd[2*i+1]);
        float4 o;
        o.x = RATIO*(__expf(a.x  - off) + EPSRF);
        o.y = RATIO*(__expf(a.y  - off) + EPSRF);
        o.z = RATIO*(__expf(c2.x - off) + EPSRF);
        o.w = RATIO*(__expf(c2.y - off) + EPSRF);
        *(float4*)&g_phiq[base + 4*i] = o;
    }

    sq = 0.f;
    #pragma unroll
    for (int c = 0; c < DD; c++) { float v = SFAC*(g_A2[n*DD+c] + c2s[c]); nv[c] = v; sq += v*v; }
    diag = 0.5f*sq;
    #pragma unroll
    for (int i = 0; i < 32; i++) dd[i] = 0ull;
    #pragma unroll 4
    for (int c = 0; c < DD; c++) {
        ull s = splat2(nv[c]);
        const ulonglong2* pp = (const ulonglong2*)&psT[c*MM];
        #pragma unroll
        for (int i = 0; i < 16; i++) {
            ulonglong2 pv = pp[i];
            fma2(dd[2*i],   s, pv.x);
            fma2(dd[2*i+1], s, pv.y);
        }
    }
    off = diag + g_stabk[b];
    #pragma unroll
    for (int i = 0; i < 16; i++) {
        float2 a = unpack2(dd[2*i]), c2 = unpack2(dd[2*i+1]);
        float4 o;
        o.x = RATIO*(__expf(a.x  - off) + EPSRF);
        o.y = RATIO*(__expf(a.y  - off) + EPSRF);
        o.z = RATIO*(__expf(c2.x - off) + EPSRF);
        o.w = RATIO*(__expf(c2.y - off) + EPSRF);
        *(float4*)&g_phik[base + 4*i] = o;
    }
}

__global__ void k_input(const float* __restrict__ x,
                        const float* __restrict__ input_w,
                        const float* __restrict__ node_emb)
{
    int b = blockIdx.y, t = threadIdx.x;
    __shared__ float wts[TT*DD];
    __shared__ float mk[DD], tv[DD], wv[DD];
    for (int i = t; i < TT*DD; i += 128) {
        int tt = i / DD, c = i % DD;
        wts[i] = input_w[c*(3*TT)+tt];
    }
    if (t < DD) { mk[t] = g_mark[b*DD+t]; tv[t] = g_tvv[b*DD+t]; wv[t] = g_wvv[b*DD+t]; }
    __syncthreads();
    int n = blockIdx.x*128 + t;
    if (n >= NN) return;
    float acc[DD];
    #pragma unroll
    for (int c = 0; c < DD; c++) acc[c] = mk[c];
    for (int tt = 0; tt < TT; tt++) {
        float xv = x[((size_t)b*TT + tt)*NN + n];
        #pragma unroll
        for (int c = 0; c < DD; c++) acc[c] += xv * wts[tt*DD+c];
    }
    size_t base = ((size_t)(b*NN) + n) * CC;
    #pragma unroll
    for (int i = 0; i < 8; i++) {
        float4 v = make_float4(acc[4*i], acc[4*i+1], acc[4*i+2], acc[4*i+3]);
        *(float4*)&g_h[base + 4*i] = v; *(float4*)&g_skip[base + 4*i] = v;
    }
    #pragma unroll
    for (int i = 0; i < 8; i++) {
        float4 v = *(const float4*)&node_emb[n*DD + 4*i];
        *(float4*)&g_h[base + DD + 4*i] = v; *(float4*)&g_skip[base + DD + 4*i] = v;
    }
    #pragma unroll
    for (int i = 0; i < 8; i++) {
        float4 v = make_float4(tv[4*i], tv[4*i+1], tv[4*i+2], tv[4*i+3]);
        *(float4*)&g_h[base + 2*DD + 4*i] = v; *(float4*)&g_skip[base + 2*DD + 4*i] = v;
    }
    #pragma unroll
    for (int i = 0; i < 8; i++) {
        float4 v = make_float4(wv[4*i], wv[4*i+1], wv[4*i+2], wv[4*i+3]);
        *(float4*)&g_h[base + 3*DD + 4*i] = v; *(float4*)&g_skip[base + 3*DD + 4*i] = v;
    }
}

__global__ void k_ksum()
{
    int ch = blockIdx.x, b = blockIdx.y, t = threadIdx.x;
    int m = t & 63, sub = t >> 6;
    int n0 = ch*CHSZ;
    float acc = 0.f;
    for (int n = n0 + sub; n < n0 + CHSZ; n += 4)
        acc += g_phik[((size_t)(b*NN) + n)*MM + m];
    __shared__ float red[256];
    red[t] = acc;
    __syncthreads();
    if (t < 64)
        g_kspart[(b*NCH+ch)*MM + m] = red[m] + red[64+m] + red[128+m] + red[192+m];
}

__global__ void k_ksumred()
{
    int b = blockIdx.x, m = threadIdx.x;
    float s = 0.f;
    for (int ch = 0; ch < NCH; ch++) s += g_kspart[(b*NCH+ch)*MM + m];
    g_ksum[b*MM+m] = s;
}

__global__ void k_den()
{
    int b = blockIdx.y, t = threadIdx.x;
    __shared__ float ks[MM];
    if (t < MM) ks[t] = g_ksum[b*MM+t];
    __syncthreads();
    int n = blockIdx.x*128 + t;
    if (n >= NN) return;
    size_t base = ((size_t)(b*NN) + n)*MM;
    float d = 0.f;
    #pragma unroll
    for (int m = 0; m < MM; m++) d += g_phiq[base+m]*ks[m];
    g_den[b*NN+n] = d;
}

// ---------------- fused gate (bf16-split HMMA) + kv-partial ------------------
#define STR   136                       // bf16 elems per row
#define TSZ   (128*STR*2)               // 34816 B per tile
#define SMEM_GATE (6*TSZ)               // 208896 B
#define USTRIDE 132

__device__ __forceinline__ void split_store(char* hiP, char* loP, float4 a, float4 c){
    float av[8] = {a.x,a.y,a.z,a.w,c.x,c.y,c.z,c.w};
    float l[8];
    #pragma unroll
    for (int j = 0; j < 8; j++) {
        float hb = __bfloat162float(__float2bfloat16(av[j]));
        l[j] = av[j] - hb;
    }
    uint4 hi, lo;
    hi.x = packbf(av[0],av[1]); hi.y = packbf(av[2],av[3]);
    hi.z = packbf(av[4],av[5]); hi.w = packbf(av[6],av[7]);
    lo.x = packbf(l[0],l[1]);   lo.y = packbf(l[2],l[3]);
    lo.z = packbf(l[4],l[5]);   lo.w = packbf(l[6],l[7]);
    *(uint4*)hiP = hi;
    *(uint4*)loP = lo;
}

__global__ __launch_bounds__(512)
void k_gatekv(const float* __restrict__ in_b,
              const float* __restrict__ out_b,
              int layer)
{
    extern __shared__ __align__(16) char smem[];
    char* AH = smem;
    char* AL = smem + TSZ;
    char* IH = smem + 2*TSZ;
    char* IL = smem + 3*TSZ;
    char* OH = smem + 4*TSZ;
    char* OL = smem + 5*TSZ;

    int t = threadIdx.x;
    int wid = t >> 5, lid = t & 31;
    int lane4 = lid >> 2, lanem = lid & 3;
    int blk = blockIdx.x, b = blockIdx.y;
    int n0 = blk*128;
    size_t batchBase = (size_t)b*NN;

    // ---- A: load + convert h to bf16 hi/lo ----
    #pragma unroll
    for (int it = 0; it < 4; it++) {
        int lin = t + it*512;
        int row = lin >> 4, seg = lin & 15;
        int c8 = seg*8;
        int boff = row*(STR*2) + c8*2;
        int nrow = min(n0 + row, NN-1);
        float4 a = *(const float4*)&g_h[(batchBase + nrow)*CC + c8];
        float4 c = *(const float4*)&g_h[(batchBase + nrow)*CC + c8 + 4];
        split_store(AH + boff, AL + boff, a, c);
    }
    // ---- W: copy prebaked bf16 hi/lo tiles from gmem ----
    #pragma unroll
    for (int it = 0; it < 4; it++) {
        int lin = t + it*512;
        int row = lin >> 4, seg = lin & 15;
        int c8 = seg*8;
        int boff = row*(STR*2) + c8*2;
        int gidx = layer*(CC*CC/8) + row*16 + seg;
        *(uint4*)(IH + boff) = g_wih[gidx];
        *(uint4*)(IL + boff) = g_wil[gidx];
        *(uint4*)(OH + boff) = g_woh[gidx];
        *(uint4*)(OL + boff) = g_wol[gidx];
    }
    __syncthreads();

    int mrow = (wid & 3)*32;
    int ncol = (wid >> 2)*32;

    float di[2][4][4], dq[2][4][4];
    #pragma unroll
    for (int mt = 0; mt < 2; mt++)
        #pragma unroll
        for (int nt = 0; nt < 4; nt++)
            #pragma unroll
            for (int j = 0; j < 4; j++) { di[mt][nt][j] = 0.f; dq[mt][nt][j] = 0.f; }

    #pragma unroll
    for (int kk = 0; kk < 8; kk++) {
        int k0 = kk*16;
        uint32_t a[2][4];
        #pragma unroll
        for (int mt = 0; mt < 2; mt++) {
            int r = mrow + mt*16 + lane4;
            int cidx = k0 + lanem*2;
            a[mt][0] = lds_u32(AH, r*STR + cidx);
            a[mt][1] = lds_u32(AH, (r+8)*STR + cidx);
            a[mt][2] = lds_u32(AH, r*STR + cidx + 8);
            a[mt][3] = lds_u32(AH, (r+8)*STR + cidx + 8);
        }
        #pragma unroll
        for (int nt = 0; nt < 4; nt++) {
            int nr = ncol + nt*8 + lane4;
            int koff = k0 + lanem*2;
            uint32_t bih[2] = { lds_u32(IH, nr*STR + koff), lds_u32(IH, nr*STR + koff + 8) };
            uint32_t boh[2] = { lds_u32(OH, nr*STR + koff), lds_u32(OH, nr*STR + koff + 8) };
            uint32_t bil[2] = { lds_u32(IL, nr*STR + koff), lds_u32(IL, nr*STR + koff + 8) };
            uint32_t bol[2] = { lds_u32(OL, nr*STR + koff), lds_u32(OL, nr*STR + koff + 8) };
            mma_bf16(di[0][nt], a[0], bih); mma_bf16(di[1][nt], a[1], bih);
            mma_bf16(dq[0][nt], a[0], boh); mma_bf16(dq[1][nt], a[1], boh);
            mma_bf16(di[0][nt], a[0], bil); mma_bf16(di[1][nt], a[1], bil);
            mma_bf16(dq[0][nt], a[0], bol); mma_bf16(dq[1][nt], a[1], bol);
        }
    }
    #pragma unroll
    for (int kk = 0; kk < 8; kk++) {
        int k0 = kk*16;
        uint32_t a[2][4];
        #pragma unroll
        for (int mt = 0; mt < 2; mt++) {
            int r = mrow + mt*16 + lane4;
            int cidx = k0 + lanem*2;
            a[mt][0] = lds_u32(AL, r*STR + cidx);
            a[mt][1] = lds_u32(AL, (r+8)*STR + cidx);
            a[mt][2] = lds_u32(AL, r*STR + cidx + 8);
            a[mt][3] = lds_u32(AL, (r+8)*STR + cidx + 8);
        }
        #pragma unroll
        for (int nt = 0; nt < 4; nt++) {
            int nr = ncol + nt*8 + lane4;
            int koff = k0 + lanem*2;
            uint32_t bih[2] = { lds_u32(IH, nr*STR + koff), lds_u32(IH, nr*STR + koff + 8) };
            uint32_t boh[2] = { lds_u32(OH, nr*STR + koff), lds_u32(OH, nr*STR + koff + 8) };
            mma_bf16(di[0][nt], a[0], bih); mma_bf16(di[1][nt], a[1], bih);
            mma_bf16(dq[0][nt], a[0], boh); mma_bf16(dq[1][nt], a[1], boh);
        }
    }
    __syncthreads();   // all tile reads done; safe to overwrite with U / PK

    float* U  = (float*)smem;            // 128 x USTRIDE fp32 (reuses AH+AL)
    float* PK = (float*)(smem + 2*TSZ);  // 128 x 64 fp32 (reuses IH)
    #pragma unroll
    for (int mt = 0; mt < 2; mt++) {
        #pragma unroll
        for (int half = 0; half < 2; half++) {
            int row = mrow + mt*16 + lane4 + half*8;
            bool ok = (n0 + row) < NN;
            #pragma unroll
            for (int nt = 0; nt < 4; nt++) {
                int col = ncol + nt*8 + lanem*2;
                float2 bi2 = *(const float2*)&in_b [layer*CC + col];
                float2 bo2 = *(const float2*)&out_b[layer*CC + col];
                float v0 = di[mt][nt][half*2+0] + bi2.x;
                float v1 = di[mt][nt][half*2+1] + bi2.y;
                float2 uv;
                uv.x = ok ? (dq[mt][nt][half*2+0]+bo2.x) / (1.f+__expf(-v0)) : 0.f;
                uv.y = ok ? (dq[mt][nt][half*2+1]+bo2.y) / (1.f+__expf(-v1)) : 0.f;
                *(float2*)&U[row*USTRIDE + col] = uv;
            }
        }
    }
    #pragma unroll
    for (int it = 0; it < 4; it++) {
        int i = t + it*512;
        int row = i >> 4, m4 = (i & 15)*4;
        int n = n0 + row;
        float4 v = make_float4(0.f,0.f,0.f,0.f);
        if (n < NN) v = *(const float4*)&g_phik[(batchBase + n)*MM + m4];
        *(float4*)&PK[row*64 + m4] = v;
    }
    __syncthreads();

    // ---- kv partial: [64 m x 128 c] = PK^T @ U ----
    // warp (wid&7) owns m = (wid&7)*8..+7, all 128 c (lane*4); row-half = wid>>3.
    {
        int wid2 = wid & 7, half = wid >> 3;
        int m0 = wid2*8;
        int r0 = half*64;
        ull acc[8][2];
        #pragma unroll
        for (int i = 0; i < 8; i++) { acc[i][0] = 0ull; acc[i][1] = 0ull; }
        #pragma unroll 4
        for (int row = r0; row < r0+64; row++) {
            float4 pm0 = *(const float4*)&PK[row*64 + m0];
            float4 pm1 = *(const float4*)&PK[row*64 + m0 + 4];
            ulonglong2 uc = *(const ulonglong2*)&U[row*USTRIDE + lid*4];
            float pm[8] = {pm0.x,pm0.y,pm0.z,pm0.w,pm1.x,pm1.y,pm1.z,pm1.w};
            #pragma unroll
            for (int i = 0; i < 8; i++) {
                ull s = splat2(pm[i]);
                fma2(acc[i][0], s, uc.x);
                fma2(acc[i][1], s, uc.y);
            }
        }
        float* SC = (float*)(smem + 4*TSZ);   // 64 x 128 fp32 scratch (reuses OH)
        if (half == 1) {
            #pragma unroll
            for (int i = 0; i < 8; i++) {
                *(ull*)&SC[(m0+i)*128 + lid*4]     = acc[i][0];
                *(ull*)&SC[(m0+i)*128 + lid*4 + 2] = acc[i][1];
            }
        }
        __syncthreads();
        if (half == 0) {
            float* dst = &g_kvpart[((size_t)(b*NBLK) + blk)*MM*CC];
            #pragma unroll
            for (int i = 0; i < 8; i++) {
                float2 a0 = unpack2(acc[i][0]), a1 = unpack2(acc[i][1]);
                float4 s4 = *(const float4*)&SC[(m0+i)*128 + lid*4];
                float4 o;
                o.x = a0.x + s4.x; o.y = a0.y + s4.y;
                o.z = a1.x + s4.z; o.w = a1.y + s4.w;
                *(float4*)&dst[(m0+i)*CC + lid*4] = o;
            }
        }
    }
}

__global__ void k_kvred()
{
    int b = blockIdx.y, t = threadIdx.x;       // grid (32, BB), 256 thr
    int i = blockIdx.x*256 + t;
    float s = 0.f;
    for (int blk = 0; blk < NBLK; blk++)
        s += g_kvpart[((size_t)(b*NBLK) + blk)*MM*CC + i];
    g_kv[b*MM*CC + i] = s;
}

// ---------------- num GEMM + divide + residual + LN (fused, f32x2) ---------
#define SMEM_NUM ((8192 + 8320) * 4)
__global__ __launch_bounds__(256) void k_num(const float* __restrict__ ln_g,
                                             const float* __restrict__ ln_b,
                                             int layer)
{
    extern __shared__ float sm[];
    float* kvs = sm;
    float* pqs = sm + 8192;
    int b = blockIdx.y, t = threadIdx.x;
    int nbase = blockIdx.x*128;

    for (int i = t; i < MM*CC; i += 256) kvs[i] = g_kv[b*MM*CC + i];
    for (int i = t; i < 128*16; i += 256) {
        int row = i >> 4, m4 = (i & 15)*4;
        int n = nbase + row;
        float4 v = make_float4(0.f,0.f,0.f,0.f);
        if (n < NN) v = *(const float4*)&g_phiq[((size_t)(b*NN)+n)*MM + m4];
        pqs[row*65+m4]   = v.x; pqs[row*65+m4+1] = v.y;
        pqs[row*65+m4+2] = v.z; pqs[row*65+m4+3] = v.w;
    }
    __syncthreads();

    int rg = t >> 4, cg = t & 15;
    ull acc[8][4];
    #pragma unroll
    for (int r = 0; r < 8; r++)
        #pragma unroll
        for (int q = 0; q < 4; q++) acc[r][q] = 0ull;
    const float* pr = &pqs[rg*8*65];
    for (int m = 0; m < MM; m++) {
        ulonglong2 u0 = *(const ulonglong2*)&kvs[m*CC + cg*8];
        ulonglong2 u1 = *(const ulonglong2*)&kvs[m*CC + cg*8 + 4];
        ull bp[4] = {u0.x, u0.y, u1.x, u1.y};
        #pragma unroll
        for (int r = 0; r < 8; r++) {
            ull as = splat2(pr[r*65 + m]);
            #pragma unroll
            for (int q = 0; q < 4; q++) fma2(acc[r][q], as, bp[q]);
        }
    }

    float* stage = pqs;
    int w = t >> 5, lane = t & 31;
    for (int half = 0; half < 2; half++) {
        __syncthreads();
        if ((rg >> 3) == half) {
            int r0 = (rg & 7)*8;
            #pragma unroll
            for (int r = 0; r < 8; r++)
                #pragma unroll
                for (int q = 0; q < 4; q++)
                    *(ull*)&stage[(r0+r)*128 + cg*8 + 2*q] = acc[r][q];
        }
        __syncthreads();
        #pragma unroll
        for (int rr = 0; rr < 8; rr++) {
            int lrow = w*8 + rr;
            int n = nbase + half*64 + lrow;
            float4 nv4 = *(const float4*)&stage[lrow*128 + lane*4];
            float4 h4 = make_float4(0.f,0.f,0.f,0.f);
            float den = 1.f;
            size_t idx = ((size_t)(b*NN) + n)*CC + lane*4;
            if (n < NN) { h4 = *(const float4*)&g_h[idx]; den = g_den[b*NN+n]; }
            float r_ = 1.0f / den;
            float v0 = nv4.x*r_ + h4.x, v1 = nv4.y*r_ + h4.y;
            float v2 = nv4.z*r_ + h4.z, v3 = nv4.w*r_ + h4.w;
            float s  = v0+v1+v2+v3;
            float s2 = v0*v0+v1*v1+v2*v2+v3*v3;
            #pragma unroll
            for (int o = 16; o; o >>= 1) {
                s  += __shfl_xor_sync(0xffffffffu, s,  o);
                s2 += __shfl_xor_sync(0xffffffffu, s2, o);
            }
            float mu  = s * (1.0f/128.0f);
            float var = s2 * (1.0f/128.0f) - mu*mu;
            float is  = rsqrtf(var + 1e-5f);
            if (n < NN) {
                float4 g4 = *(const float4*)&ln_g[layer*CC + lane*4];
                float4 b4 = *(const float4*)&ln_b[layer*CC + lane*4];
                float4 o4;
                o4.x = (v0-mu)*is*g4.x + b4.x;
                o4.y = (v1-mu)*is*g4.y + b4.y;
                o4.z = (v2-mu)*is*g4.z + b4.z;
                o4.w = (v3-mu)*is*g4.w + b4.w;
                *(float4*)&g_h[idx] = o4;
            }
        }
    }
}

// ---------------- regression head ----------------
__global__ void k_reg(const float* __restrict__ reg_w,
                      const float* __restrict__ reg_b,
                      float* __restrict__ out)
{
    int b = blockIdx.y, t = threadIdx.x;
    __shared__ float rw[PP*2*CC];
    __shared__ float st[128*33];
    for (int i = t; i < PP*2*CC; i += 128) rw[i] = reg_w[i];
    int nbase = blockIdx.x*128;
    float acc[PP];
    #pragma unroll
    for (int p = 0; p < PP; p++) acc[p] = 0.f;
    for (int src = 0; src < 2; src++) {
        const float* S = src ? g_h : g_skip;
        for (int c0 = 0; c0 < CC; c0 += 32) {
            __syncthreads();
            #pragma unroll
            for (int k = 0; k < 32; k++) {
                int lin = t + k*128;
                int rr = lin >> 5, cc = lin & 31;
                int n = nbase + rr;
                st[rr*33+cc] = (n < NN) ? S[((size_t)(b*NN) + n)*CC + c0 + cc] : 0.f;
            }
            __syncthreads();
            #pragma unroll
            for (int cc = 0; cc < 32; cc++) {
                float v = st[t*33+cc];
                #pragma unroll
                for (int p = 0; p < PP; p++)
                    acc[p] += v * rw[p*(2*CC) + src*CC + c0 + cc];
            }
        }
    }
    int n = nbase + t;
    if (n < NN) {
        #pragma unroll
        for (int p = 0; p < PP; p++)
            out[((size_t)(b*PP) + p)*NN + n] = acc[p] + reg_b[p];
    }
}

// ---------------- launcher ----------------
extern "C" void kernel_launch(void* const* d_in, const int* in_sizes, int n_in,
                              void* d_out, int out_size)
{
    const float* x        = (const float*)d_in[0];
    const float* xmark    = (const float*)d_in[1];
    const float* node_emb = (const float*)d_in[2];
    const float* time_tab = (const float*)d_in[3];
    const float* week_tab = (const float*)d_in[4];
    const float* input_w  = (const float*)d_in[5];
    const float* input_b  = (const float*)d_in[6];
    const float* w1_w     = (const float*)d_in[7];
    const float* w1_b     = (const float*)d_in[8];
    const float* w2_w     = (const float*)d_in[9];
    const float* w2_b     = (const float*)d_in[10];
    const float* in_w     = (const float*)d_in[11];
    const float* in_b     = (const float*)d_in[12];
    const float* out_w    = (const float*)d_in[13];
    const float* out_b    = (const float*)d_in[14];
    const float* ln_g     = (const float*)d_in[15];
    const float* ln_b     = (const float*)d_in[16];
    const float* reg_w    = (const float*)d_in[17];
    const float* reg_b    = (const float*)d_in[18];
    const float* proj     = (const float*)d_in[19];
    float* out = (float*)d_out;

    cudaFuncSetAttribute(k_num,    cudaFuncAttributeMaxDynamicSharedMemorySize, SMEM_NUM);
    cudaFuncSetAttribute(k_gatekv, cudaFuncAttributeMaxDynamicSharedMemorySize, SMEM_GATE);

    dim3 gBN(NBLK, BB);

    k_wprep<<<LL, 256>>>(in_w, out_w);
    k_const<<<BB, 128>>>(xmark, time_tab, week_tab, input_w, input_b,
                         w1_w, w1_b, w2_w, w2_b, proj);
    k_node<<<(NN + 255)/256, 256>>>(node_emb, w1_w, w2_w);
    k_colmax<<<MM, 256>>>(proj);
    k_stab<<<BB, 64>>>();
    k_phi<<<gBN, 128>>>(proj);
    k_input<<<gBN, 128>>>(x, input_w, node_emb);
    k_ksum<<<dim3(NCH, BB), 256>>>();
    k_ksumred<<<BB, 64>>>();
    k_den<<<gBN, 128>>>();

    for (int l = 0; l < LL; l++) {
        k_gatekv<<<gBN, 512, SMEM_GATE>>>(in_b, out_b, l);
        k_kvred<<<dim3(32, BB), 256>>>();
        k_num<<<gBN, 256, SMEM_NUM>>>(ln_g, ln_b, l);
    }
    k_reg<<<gBN, 128>>>(reg_w, reg_b, out);
}

// round 15
// speedup vs baseline: 1.1867x; 1.1677x over previous
#include <cuda_runtime.h>
#include <cuda_bf16.h>
#include <math.h>
#include <stdint.h>

// Problem constants
#define BB 8
#define TT 96
#define NN 20000
#define PP 12
#define LL 3
#define DD 32
#define CC 128
#define MM 64
#define NBLK 157              // ceil(NN/128) row-blocks per batch
#define NCH 100               // node chunks for ksum/colmax partials
#define CHSZ (NN/NCH)         // 200

#define SFAC 0.4204482076268573f   // 32^{-1/4}
#define RATIO 0.125f               // 1/sqrt(64)
#define EPSRF 1e-6f

typedef unsigned long long ull;

// ---- packed fp32x2 helpers ----
__device__ __forceinline__ ull splat2(float v){
    ull r; asm("mov.b64 %0, {%1, %1};" : "=l"(r) : "f"(v)); return r;
}
__device__ __forceinline__ void fma2(ull& acc, ull a, ull b){
    asm("fma.rn.f32x2 %0, %1, %2, %0;" : "+l"(acc) : "l"(a), "l"(b));
}
__device__ __forceinline__ float2 unpack2(ull v){
    float2 f; asm("mov.b64 {%0, %1}, %2;" : "=f"(f.x), "=f"(f.y) : "l"(v)); return f;
}

// ---- HMMA helper: base-ISA bf16 mma (compiles for compute_103) ----
__device__ __forceinline__ void mma_bf16(float d[4], const uint32_t a[4], const uint32_t b[2]){
    asm volatile("mma.sync.aligned.m16n8k16.row.col.f32.bf16.bf16.f32 "
        "{%0,%1,%2,%3}, {%4,%5,%6,%7}, {%8,%9}, {%0,%1,%2,%3};"
        : "+f"(d[0]), "+f"(d[1]), "+f"(d[2]), "+f"(d[3])
        : "r"(a[0]), "r"(a[1]), "r"(a[2]), "r"(a[3]), "r"(b[0]), "r"(b[1]));
}
__device__ __forceinline__ uint32_t packbf(float a, float b){
    __nv_bfloat162 h = __floats2bfloat162_rn(a, b);
    uint32_t r; memcpy(&r, &h, 4); return r;
}
__device__ __forceinline__ uint32_t lds_u32(const char* base, int elem){   // elem in bf16 units
    return *(const uint32_t*)(base + elem*2);
}

// ---------------- device scratch ----------
__device__ float g_h   [(size_t)BB*NN*CC];
__device__ float g_skip[(size_t)BB*NN*CC];
__device__ float g_phiq[(size_t)BB*NN*MM];
__device__ float g_phik[(size_t)BB*NN*MM];
__device__ float g_A1[NN*DD];
__device__ float g_A2[NN*DD];
__device__ float g_c1[BB*DD];
__device__ float g_c2[BB*DD];
__device__ float g_Pc2[BB*MM];
__device__ float g_mark[BB*DD];
__device__ float g_tvv[BB*DD];
__device__ float g_wvv[BB*DD];
__device__ float g_cmpart[NCH*MM];
__device__ float g_stabk[BB];
__device__ float g_kvpart[(size_t)BB*NBLK*MM*CC];
__device__ float g_kv[BB*MM*CC];
__device__ float g_kspart[BB*NCH*MM];
__device__ float g_ksum[BB*MM];
__device__ float g_den[BB*NN];
// prebaked bf16 hi/lo weight tiles: [layer][row][c], packed 8 bf16 per uint4
__device__ uint4 g_wih[LL*CC*CC/8];
__device__ uint4 g_wil[LL*CC*CC/8];
__device__ uint4 g_woh[LL*CC*CC/8];
__device__ uint4 g_wol[LL*CC*CC/8];

// ---------------- weight prebake (bf16 hi/lo split) ----------------
__global__ void k_wprep(const float* __restrict__ in_w,
                        const float* __restrict__ out_w)
{
    int layer = blockIdx.x, t = threadIdx.x;
    const float* IW = in_w  + (size_t)layer*CC*CC;
    const float* OW = out_w + (size_t)layer*CC*CC;
    for (int i = t; i < CC*CC/8; i += 256) {
        {
            float4 a = *(const float4*)&IW[i*8];
            float4 c = *(const float4*)&IW[i*8 + 4];
            float av[8] = {a.x,a.y,a.z,a.w,c.x,c.y,c.z,c.w}, l[8];
            #pragma unroll
            for (int j = 0; j < 8; j++) {
                float hb = __bfloat162float(__float2bfloat16(av[j]));
                l[j] = av[j] - hb;
            }
            uint4 hi, lo;
            hi.x = packbf(av[0],av[1]); hi.y = packbf(av[2],av[3]);
            hi.z = packbf(av[4],av[5]); hi.w = packbf(av[6],av[7]);
            lo.x = packbf(l[0],l[1]);   lo.y = packbf(l[2],l[3]);
            lo.z = packbf(l[4],l[5]);   lo.w = packbf(l[6],l[7]);
            g_wih[layer*(CC*CC/8) + i] = hi;
            g_wil[layer*(CC*CC/8) + i] = lo;
        }
        {
            float4 a = *(const float4*)&OW[i*8];
            float4 c = *(const float4*)&OW[i*8 + 4];
            float av[8] = {a.x,a.y,a.z,a.w,c.x,c.y,c.z,c.w}, l[8];
            #pragma unroll
            for (int j = 0; j < 8; j++) {
                float hb = __bfloat162float(__float2bfloat16(av[j]));
                l[j] = av[j] - hb;
            }
            uint4 hi, lo;
            hi.x = packbf(av[0],av[1]); hi.y = packbf(av[2],av[3]);
            hi.z = packbf(av[4],av[5]); hi.w = packbf(av[6],av[7]);
            lo.x = packbf(l[0],l[1]);   lo.y = packbf(l[2],l[3]);
            lo.z = packbf(l[4],l[5]);   lo.w = packbf(l[6],l[7]);
            g_woh[layer*(CC*CC/8) + i] = hi;
            g_wol[layer*(CC*CC/8) + i] = lo;
        }
    }
}

// ---------------- per-batch constants -----------------
__global__ void k_const(const float* __restrict__ xmark,
                        const float* __restrict__ time_tab,
                        const float* __restrict__ week_tab,
                        const float* __restrict__ input_w,
                        const float* __restrict__ input_b,
                        const float* __restrict__ w1_w, const float* __restrict__ w1_b,
                        const float* __restrict__ w2_w, const float* __restrict__ w2_b,
                        const float* __restrict__ proj)
{
    int b = blockIdx.x, t = threadIdx.x;
    __shared__ float xm0[TT], xm1[TT], stv[DD], swv[DD], sc1[DD], sc2[DD];

    float m0 = xmark[(b*TT + (TT-1))*2 + 0];
    float m1 = xmark[(b*TT + (TT-1))*2 + 1];
    int tod = (int)(m0 * (float)TT); tod = min(max(tod, 0), TT-1);
    int dow = (int)(m1 * 7.0f);      dow = min(max(dow, 0), 6);

    if (t < TT) { xm0[t] = xmark[(b*TT+t)*2]; xm1[t] = xmark[(b*TT+t)*2+1]; }
    if (t < DD) {
        float tv = time_tab[tod*DD+t], wv = week_tab[dow*DD+t];
        stv[t] = tv; swv[t] = wv;
        g_tvv[b*DD+t] = tv; g_wvv[b*DD+t] = wv;
    }
    __syncthreads();
    if (t < DD) {
        float mc = input_b[t];
        for (int k = 0; k < TT; k++)
            mc += xm0[k]*input_w[t*(3*TT)+TT+k] + xm1[k]*input_w[t*(3*TT)+2*TT+k];
        g_mark[b*DD+t] = mc;
        float v1 = w1_b[t], v2 = w2_b[t];
        for (int g = 0; g < DD; g++) {
            v1 += stv[g]*w1_w[t*(3*DD)+DD+g] + swv[g]*w1_w[t*(3*DD)+2*DD+g];
            v2 += stv[g]*w2_w[t*(3*DD)+DD+g] + swv[g]*w2_w[t*(3*DD)+2*DD+g];
        }
        v1 *= 2.0f; v2 *= 2.0f;
        sc1[t] = v1; sc2[t] = v2;
        g_c1[b*DD+t] = v1; g_c2[b*DD+t] = v2;
    }
    __syncthreads();
    if (t < MM) {
        float p = 0.f;
        #pragma unroll
        for (int c = 0; c < DD; c++) p += sc2[c]*proj[t*DD+c];
        g_Pc2[b*MM+t] = SFAC * p;
    }
}

__global__ void k_node(const float* __restrict__ node_emb,
                       const float* __restrict__ w1_w,
                       const float* __restrict__ w2_w)
{
    __shared__ float w1s[DD*DD], w2s[DD*DD];
    int t = threadIdx.x;
    for (int i = t; i < DD*DD; i += 256) {
        int c = i / DD, g = i % DD;
        w1s[i] = w1_w[c*(3*DD)+g];
        w2s[i] = w2_w[c*(3*DD)+g];
    }
    __syncthreads();
    int n = blockIdx.x*256 + t;
    if (n >= NN) return;
    float ne[DD];
    #pragma unroll
    for (int g = 0; g < DD; g++) ne[g] = node_emb[n*DD+g];
    #pragma unroll 4
    for (int c = 0; c < DD; c++) {
        float a1 = 0.f, a2 = 0.f;
        #pragma unroll
        for (int g = 0; g < DD; g++) { a1 += ne[g]*w1s[c*DD+g]; a2 += ne[g]*w2s[c*DD+g]; }
        g_A1[n*DD+c] = 2.0f*a1;
        g_A2[n*DD+c] = 2.0f*a2;
    }
}

// ---------------- colmax partials: per-chunk max_n of A2 . proj[m] ----------
__global__ __launch_bounds__(256) void k_colmax_part(const float* __restrict__ proj)
{
    int ch = blockIdx.x, t = threadIdx.x;  // 256 threads
    __shared__ float psT[DD*MM];           // transposed [c][m]
    __shared__ float red[256];
    for (int i = t; i < DD*MM; i += 256) {
        int m = i >> 5, c = i & 31;
        psT[c*MM+m] = proj[m*DD+c];
    }
    __syncthreads();
    int m = t & 63, sub = t >> 6;          // 4 subs x 64 m
    int n0 = ch*CHSZ;
    float mx = -1e30f;
    for (int n = n0 + sub; n < n0 + CHSZ; n += 4) {
        float d = 0.f;
        #pragma unroll
        for (int c = 0; c < DD; c++) d += g_A2[n*DD+c]*psT[c*MM+m];
        mx = fmaxf(mx, d);
    }
    red[t] = mx;
    __syncthreads();
    if (t < 64)
        g_cmpart[ch*MM + m] =
            fmaxf(fmaxf(red[m], red[64+m]), fmaxf(red[128+m], red[192+m]));
}

__global__ void k_stab()
{
    int b = blockIdx.x, t = threadIdx.x;   // 64 threads
    __shared__ float red[2];
    float cm = -1e30f;
    for (int ch = 0; ch < NCH; ch++) cm = fmaxf(cm, g_cmpart[ch*MM + t]);
    float v = SFAC*cm + g_Pc2[b*MM+t];
    for (int o = 16; o; o >>= 1) v = fmaxf(v, __shfl_down_sync(0xffffffffu, v, o));
    if ((t & 31) == 0) red[t >> 5] = v;
    __syncthreads();
    if (t == 0) g_stabk[b] = fmaxf(red[0], red[1]);
}

__global__ __launch_bounds__(128) void k_phi(const float* __restrict__ proj)
{
    int b = blockIdx.y, t = threadIdx.x;
    __shared__ float psT[DD*MM];
    __shared__ float c1s[DD], c2s[DD];
    for (int i = t; i < DD*MM; i += 128) {
        int m = i >> 5, c = i & 31;
        psT[c*MM+m] = proj[m*DD+c];
    }
    if (t < DD) { c1s[t] = g_c1[b*DD+t]; c2s[t] = g_c2[b*DD+t]; }
    __syncthreads();
    int n = blockIdx.x*128 + t;
    if (n >= NN) return;

    size_t base = ((size_t)(b*NN) + n) * MM;
    ull dd[32];
    float nv[DD];

    float sq = 0.f;
    #pragma unroll
    for (int c = 0; c < DD; c++) { float v = SFAC*(g_A1[n*DD+c] + c1s[c]); nv[c] = v; sq += v*v; }
    float diag = 0.5f*sq;
    #pragma unroll
    for (int i = 0; i < 32; i++) dd[i] = 0ull;
    #pragma unroll 4
    for (int c = 0; c < DD; c++) {
        ull s = splat2(nv[c]);
        const ulonglong2* pp = (const ulonglong2*)&psT[c*MM];
        #pragma unroll
        for (int i = 0; i < 16; i++) {
            ulonglong2 pv = pp[i];
            fma2(dd[2*i],   s, pv.x);
            fma2(dd[2*i+1], s, pv.y);
        }
    }
    float mx = -1e30f;
    #pragma unroll
    for (int i = 0; i < 32; i++) { float2 f = unpack2(dd[i]); mx = fmaxf(mx, fmaxf(f.x, f.y)); }
    float off = diag + mx;
    #pragma unroll
    for (int i = 0; i < 16; i++) {
        float2 a = unpack2(dd[2*i]), c2 = unpack2(dd[2*i+1]);
        float4 o;
        o.x = RATIO*(__expf(a.x  - off) + EPSRF);
        o.y = RATIO*(__expf(a.y  - off) + EPSRF);
        o.z = RATIO*(__expf(c2.x - off) + EPSRF);
        o.w = RATIO*(__expf(c2.y - off) + EPSRF);
        *(float4*)&g_phiq[base + 4*i] = o;
    }

    sq = 0.f;
    #pragma unroll
    for (int c = 0; c < DD; c++) { float v = SFAC*(g_A2[n*DD+c] + c2s[c]); nv[c] = v; sq += v*v; }
    diag = 0.5f*sq;
    #pragma unroll
    for (int i = 0; i < 32; i++) dd[i] = 0ull;
    #pragma unroll 4
    for (int c = 0; c < DD; c++) {
        ull s = splat2(nv[c]);
        const ulonglong2* pp = (const ulonglong2*)&psT[c*MM];
        #pragma unroll
        for (int i = 0; i < 16; i++) {
            ulonglong2 pv = pp[i];
            fma2(dd[2*i],   s, pv.x);
            fma2(dd[2*i+1], s, pv.y);
        }
    }
    off = diag + g_stabk[b];
    #pragma unroll
    for (int i = 0; i < 16; i++) {
        float2 a = unpack2(dd[2*i]), c2 = unpack2(dd[2*i+1]);
        float4 o;
        o.x = RATIO*(__expf(a.x  - off) + EPSRF);
        o.y = RATIO*(__expf(a.y  - off) + EPSRF);
        o.z = RATIO*(__expf(c2.x - off) + EPSRF);
        o.w = RATIO*(__expf(c2.y - off) + EPSRF);
        *(float4*)&g_phik[base + 4*i] = o;
    }
}

__global__ void k_input(const float* __restrict__ x,
                        const float* __restrict__ input_w,
                        const float* __restrict__ node_emb)
{
    int b = blockIdx.y, t = threadIdx.x;
    __shared__ float wts[TT*DD];
    __shared__ float mk[DD], tv[DD], wv[DD];
    for (int i = t; i < TT*DD; i += 128) {
        int tt = i / DD, c = i % DD;
        wts[i] = input_w[c*(3*TT)+tt];
    }
    if (t < DD) { mk[t] = g_mark[b*DD+t]; tv[t] = g_tvv[b*DD+t]; wv[t] = g_wvv[b*DD+t]; }
    __syncthreads();
    int n = blockIdx.x*128 + t;
    if (n >= NN) return;
    float acc[DD];
    #pragma unroll
    for (int c = 0; c < DD; c++) acc[c] = mk[c];
    for (int tt = 0; tt < TT; tt++) {
        float xv = x[((size_t)b*TT + tt)*NN + n];
        #pragma unroll
        for (int c = 0; c < DD; c++) acc[c] += xv * wts[tt*DD+c];
    }
    size_t base = ((size_t)(b*NN) + n) * CC;
    #pragma unroll
    for (int i = 0; i < 8; i++) {
        float4 v = make_float4(acc[4*i], acc[4*i+1], acc[4*i+2], acc[4*i+3]);
        *(float4*)&g_h[base + 4*i] = v; *(float4*)&g_skip[base + 4*i] = v;
    }
    #pragma unroll
    for (int i = 0; i < 8; i++) {
        float4 v = *(const float4*)&node_emb[n*DD + 4*i];
        *(float4*)&g_h[base + DD + 4*i] = v; *(float4*)&g_skip[base + DD + 4*i] = v;
    }
    #pragma unroll
    for (int i = 0; i < 8; i++) {
        float4 v = make_float4(tv[4*i], tv[4*i+1], tv[4*i+2], tv[4*i+3]);
        *(float4*)&g_h[base + 2*DD + 4*i] = v; *(float4*)&g_skip[base + 2*DD + 4*i] = v;
    }
    #pragma unroll
    for (int i = 0; i < 8; i++) {
        float4 v = make_float4(wv[4*i], wv[4*i+1], wv[4*i+2], wv[4*i+3]);
        *(float4*)&g_h[base + 3*DD + 4*i] = v; *(float4*)&g_skip[base + 3*DD + 4*i] = v;
    }
}

__global__ void k_ksum()
{
    int ch = blockIdx.x, b = blockIdx.y, t = threadIdx.x;
    int m = t & 63, sub = t >> 6;
    int n0 = ch*CHSZ;
    float acc = 0.f;
    for (int n = n0 + sub; n < n0 + CHSZ; n += 4)
        acc += g_phik[((size_t)(b*NN) + n)*MM + m];
    __shared__ float red[256];
    red[t] = acc;
    __syncthreads();
    if (t < 64)
        g_kspart[(b*NCH+ch)*MM + m] = red[m] + red[64+m] + red[128+m] + red[192+m];
}

__global__ void k_ksumred()
{
    int b = blockIdx.x, m = threadIdx.x;
    float s = 0.f;
    for (int ch = 0; ch < NCH; ch++) s += g_kspart[(b*NCH+ch)*MM + m];
    g_ksum[b*MM+m] = s;
}

__global__ void k_den()
{
    int b = blockIdx.y, t = threadIdx.x;
    __shared__ float ks[MM];
    if (t < MM) ks[t] = g_ksum[b*MM+t];
    __syncthreads();
    int n = blockIdx.x*128 + t;
    if (n >= NN) return;
    size_t base = ((size_t)(b*NN) + n)*MM;
    float d = 0.f;
    #pragma unroll
    for (int m = 0; m < MM; m++) d += g_phiq[base+m]*ks[m];
    g_den[b*NN+n] = d;
}

// ---------------- fused gate (bf16-split HMMA) + kv-partial ------------------
#define STR   136                       // bf16 elems per row
#define TSZ   (128*STR*2)               // 34816 B per tile
#define SMEM_GATE (6*TSZ)               // 208896 B
#define USTRIDE 132

__device__ __forceinline__ void split_store(char* hiP, char* loP, float4 a, float4 c){
    float av[8] = {a.x,a.y,a.z,a.w,c.x,c.y,c.z,c.w};
    float l[8];
    #pragma unroll
    for (int j = 0; j < 8; j++) {
        float hb = __bfloat162float(__float2bfloat16(av[j]));
        l[j] = av[j] - hb;
    }
    uint4 hi, lo;
    hi.x = packbf(av[0],av[1]); hi.y = packbf(av[2],av[3]);
    hi.z = packbf(av[4],av[5]); hi.w = packbf(av[6],av[7]);
    lo.x = packbf(l[0],l[1]);   lo.y = packbf(l[2],l[3]);
    lo.z = packbf(l[4],l[5]);   lo.w = packbf(l[6],l[7]);
    *(uint4*)hiP = hi;
    *(uint4*)loP = lo;
}

__global__ __launch_bounds__(512)
void k_gatekv(const float* __restrict__ in_b,
              const float* __restrict__ out_b,
              int layer)
{
    extern __shared__ __align__(16) char smem[];
    char* AH = smem;
    char* AL = smem + TSZ;
    char* IH = smem + 2*TSZ;
    char* IL = smem + 3*TSZ;
    char* OH = smem + 4*TSZ;
    char* OL = smem + 5*TSZ;

    int t = threadIdx.x;
    int wid = t >> 5, lid = t & 31;
    int lane4 = lid >> 2, lanem = lid & 3;
    int blk = blockIdx.x, b = blockIdx.y;
    int n0 = blk*128;
    size_t batchBase = (size_t)b*NN;

    // ---- A: load + convert h to bf16 hi/lo ----
    #pragma unroll
    for (int it = 0; it < 4; it++) {
        int lin = t + it*512;
        int row = lin >> 4, seg = lin & 15;
        int c8 = seg*8;
        int boff = row*(STR*2) + c8*2;
        int nrow = min(n0 + row, NN-1);
        float4 a = *(const float4*)&g_h[(batchBase + nrow)*CC + c8];
        float4 c = *(const float4*)&g_h[(batchBase + nrow)*CC + c8 + 4];
        split_store(AH + boff, AL + boff, a, c);
    }
    // ---- W: copy prebaked bf16 hi/lo tiles from gmem ----
    #pragma unroll
    for (int it = 0; it < 4; it++) {
        int lin = t + it*512;
        int row = lin >> 4, seg = lin & 15;
        int c8 = seg*8;
        int boff = row*(STR*2) + c8*2;
        int gidx = layer*(CC*CC/8) + row*16 + seg;
        *(uint4*)(IH + boff) = g_wih[gidx];
        *(uint4*)(IL + boff) = g_wil[gidx];
        *(uint4*)(OH + boff) = g_woh[gidx];
        *(uint4*)(OL + boff) = g_wol[gidx];
    }
    __syncthreads();

    int mrow = (wid & 3)*32;
    int ncol = (wid >> 2)*32;

    float di[2][4][4], dq[2][4][4];
    #pragma unroll
    for (int mt = 0; mt < 2; mt++)
        #pragma unroll
        for (int nt = 0; nt < 4; nt++)
            #pragma unroll
            for (int j = 0; j < 4; j++) { di[mt][nt][j] = 0.f; dq[mt][nt][j] = 0.f; }

    #pragma unroll
    for (int kk = 0; kk < 8; kk++) {
        int k0 = kk*16;
        uint32_t a[2][4];
        #pragma unroll
        for (int mt = 0; mt < 2; mt++) {
            int r = mrow + mt*16 + lane4;
            int cidx = k0 + lanem*2;
            a[mt][0] = lds_u32(AH, r*STR + cidx);
            a[mt][1] = lds_u32(AH, (r+8)*STR + cidx);
            a[mt][2] = lds_u32(AH, r*STR + cidx + 8);
            a[mt][3] = lds_u32(AH, (r+8)*STR + cidx + 8);
        }
        #pragma unroll
        for (int nt = 0; nt < 4; nt++) {
            int nr = ncol + nt*8 + lane4;
            int koff = k0 + lanem*2;
            uint32_t bih[2] = { lds_u32(IH, nr*STR + koff), lds_u32(IH, nr*STR + koff + 8) };
            uint32_t boh[2] = { lds_u32(OH, nr*STR + koff), lds_u32(OH, nr*STR + koff + 8) };
            uint32_t bil[2] = { lds_u32(IL, nr*STR + koff), lds_u32(IL, nr*STR + koff + 8) };
            uint32_t bol[2] = { lds_u32(OL, nr*STR + koff), lds_u32(OL, nr*STR + koff + 8) };
            mma_bf16(di[0][nt], a[0], bih); mma_bf16(di[1][nt], a[1], bih);
            mma_bf16(dq[0][nt], a[0], boh); mma_bf16(dq[1][nt], a[1], boh);
            mma_bf16(di[0][nt], a[0], bil); mma_bf16(di[1][nt], a[1], bil);
            mma_bf16(dq[0][nt], a[0], bol); mma_bf16(dq[1][nt], a[1], bol);
        }
    }
    #pragma unroll
    for (int kk = 0; kk < 8; kk++) {
        int k0 = kk*16;
        uint32_t a[2][4];
        #pragma unroll
        for (int mt = 0; mt < 2; mt++) {
            int r = mrow + mt*16 + lane4;
            int cidx = k0 + lanem*2;
            a[mt][0] = lds_u32(AL, r*STR + cidx);
            a[mt][1] = lds_u32(AL, (r+8)*STR + cidx);
            a[mt][2] = lds_u32(AL, r*STR + cidx + 8);
            a[mt][3] = lds_u32(AL, (r+8)*STR + cidx + 8);
        }
        #pragma unroll
        for (int nt = 0; nt < 4; nt++) {
            int nr = ncol + nt*8 + lane4;
            int koff = k0 + lanem*2;
            uint32_t bih[2] = { lds_u32(IH, nr*STR + koff), lds_u32(IH, nr*STR + koff + 8) };
            uint32_t boh[2] = { lds_u32(OH, nr*STR + koff), lds_u32(OH, nr*STR + koff + 8) };
            mma_bf16(di[0][nt], a[0], bih); mma_bf16(di[1][nt], a[1], bih);
            mma_bf16(dq[0][nt], a[0], boh); mma_bf16(dq[1][nt], a[1], boh);
        }
    }
    __syncthreads();   // all tile reads done; safe to overwrite with U / PK

    float* U  = (float*)smem;            // 128 x USTRIDE fp32 (reuses AH+AL)
    float* PK = (float*)(smem + 2*TSZ);  // 128 x 64 fp32 (reuses IH)
    #pragma unroll
    for (int mt = 0; mt < 2; mt++) {
        #pragma unroll
        for (int half = 0; half < 2; half++) {
            int row = mrow + mt*16 + lane4 + half*8;
            bool ok = (n0 + row) < NN;
            #pragma unroll
            for (int nt = 0; nt < 4; nt++) {
                int col = ncol + nt*8 + lanem*2;
                float2 bi2 = *(const float2*)&in_b [layer*CC + col];
                float2 bo2 = *(const float2*)&out_b[layer*CC + col];
                float v0 = di[mt][nt][half*2+0] + bi2.x;
                float v1 = di[mt][nt][half*2+1] + bi2.y;
                float2 uv;
                uv.x = ok ? (dq[mt][nt][half*2+0]+bo2.x) / (1.f+__expf(-v0)) : 0.f;
                uv.y = ok ? (dq[mt][nt][half*2+1]+bo2.y) / (1.f+__expf(-v1)) : 0.f;
                *(float2*)&U[row*USTRIDE + col] = uv;
            }
        }
    }
    #pragma unroll
    for (int it = 0; it < 4; it++) {
        int i = t + it*512;
        int row = i >> 4, m4 = (i & 15)*4;
        int n = n0 + row;
        float4 v = make_float4(0.f,0.f,0.f,0.f);
        if (n < NN) v = *(const float4*)&g_phik[(batchBase + n)*MM + m4];
        *(float4*)&PK[row*64 + m4] = v;
    }
    __syncthreads();

    // ---- kv partial: [64 m x 128 c] = PK^T @ U ----
    {
        int wid2 = wid & 7, half = wid >> 3;
        int m0 = wid2*8;
        int r0 = half*64;
        ull acc[8][2];
        #pragma unroll
        for (int i = 0; i < 8; i++) { acc[i][0] = 0ull; acc[i][1] = 0ull; }
        #pragma unroll 4
        for (int row = r0; row < r0+64; row++) {
            float4 pm0 = *(const float4*)&PK[row*64 + m0];
            float4 pm1 = *(const float4*)&PK[row*64 + m0 + 4];
            ulonglong2 uc = *(const ulonglong2*)&U[row*USTRIDE + lid*4];
            float pm[8] = {pm0.x,pm0.y,pm0.z,pm0.w,pm1.x,pm1.y,pm1.z,pm1.w};
            #pragma unroll
            for (int i = 0; i < 8; i++) {
                ull s = splat2(pm[i]);
                fma2(acc[i][0], s, uc.x);
                fma2(acc[i][1], s, uc.y);
            }
        }
        float* SC = (float*)(smem + 4*TSZ);   // 64 x 128 fp32 scratch (reuses OH)
        if (half == 1) {
            #pragma unroll
            for (int i = 0; i < 8; i++) {
                *(ull*)&SC[(m0+i)*128 + lid*4]     = acc[i][0];
                *(ull*)&SC[(m0+i)*128 + lid*4 + 2] = acc[i][1];
            }
        }
        __syncthreads();
        if (half == 0) {
            float* dst = &g_kvpart[((size_t)(b*NBLK) + blk)*MM*CC];
            #pragma unroll
            for (int i = 0; i < 8; i++) {
                float2 a0 = unpack2(acc[i][0]), a1 = unpack2(acc[i][1]);
                float4 s4 = *(const float4*)&SC[(m0+i)*128 + lid*4];
                float4 o;
                o.x = a0.x + s4.x; o.y = a0.y + s4.y;
                o.z = a1.x + s4.z; o.w = a1.y + s4.w;
                *(float4*)&dst[(m0+i)*CC + lid*4] = o;
            }
        }
    }
}

__global__ void k_kvred()
{
    int b = blockIdx.y, t = threadIdx.x;       // grid (32, BB), 256 thr
    int i = blockIdx.x*256 + t;
    float s = 0.f;
    for (int blk = 0; blk < NBLK; blk++)
        s += g_kvpart[((size_t)(b*NBLK) + blk)*MM*CC + i];
    g_kv[b*MM*CC + i] = s;
}

// ---------------- num GEMM + divide + residual + LN (fused, f32x2) ---------
#define SMEM_NUM ((8192 + 8320) * 4)
__global__ __launch_bounds__(256) void k_num(const float* __restrict__ ln_g,
                                             const float* __restrict__ ln_b,
                                             int layer)
{
    extern __shared__ float sm[];
    float* kvs = sm;
    float* pqs = sm + 8192;
    int b = blockIdx.y, t = threadIdx.x;
    int nbase = blockIdx.x*128;

    for (int i = t; i < MM*CC; i += 256) kvs[i] = g_kv[b*MM*CC + i];
    for (int i = t; i < 128*16; i += 256) {
        int row = i >> 4, m4 = (i & 15)*4;
        int n = nbase + row;
        float4 v = make_float4(0.f,0.f,0.f,0.f);
        if (n < NN) v = *(const float4*)&g_phiq[((size_t)(b*NN)+n)*MM + m4];
        pqs[row*65+m4]   = v.x; pqs[row*65+m4+1] = v.y;
        pqs[row*65+m4+2] = v.z; pqs[row*65+m4+3] = v.w;
    }
    __syncthreads();

    int rg = t >> 4, cg = t & 15;
    ull acc[8][4];
    #pragma unroll
    for (int r = 0; r < 8; r++)
        #pragma unroll
        for (int q = 0; q < 4; q++) acc[r][q] = 0ull;
    const float* pr = &pqs[rg*8*65];
    for (int m = 0; m < MM; m++) {
        ulonglong2 u0 = *(const ulonglong2*)&kvs[m*CC + cg*8];
        ulonglong2 u1 = *(const ulonglong2*)&kvs[m*CC + cg*8 + 4];
        ull bp[4] = {u0.x, u0.y, u1.x, u1.y};
        #pragma unroll
        for (int r = 0; r < 8; r++) {
            ull as = splat2(pr[r*65 + m]);
            #pragma unroll
            for (int q = 0; q < 4; q++) fma2(acc[r][q], as, bp[q]);
        }
    }

    float* stage = pqs;
    int w = t >> 5, lane = t & 31;
    for (int half = 0; half < 2; half++) {
        __syncthreads();
        if ((rg >> 3) == half) {
            int r0 = (rg & 7)*8;
            #pragma unroll
            for (int r = 0; r < 8; r++)
                #pragma unroll
                for (int q = 0; q < 4; q++)
                    *(ull*)&stage[(r0+r)*128 + cg*8 + 2*q] = acc[r][q];
        }
        __syncthreads();
        #pragma unroll
        for (int rr = 0; rr < 8; rr++) {
            int lrow = w*8 + rr;
            int n = nbase + half*64 + lrow;
            float4 nv4 = *(const float4*)&stage[lrow*128 + lane*4];
            float4 h4 = make_float4(0.f,0.f,0.f,0.f);
            float den = 1.f;
            size_t idx = ((size_t)(b*NN) + n)*CC + lane*4;
            if (n < NN) { h4 = *(const float4*)&g_h[idx]; den = g_den[b*NN+n]; }
            float r_ = 1.0f / den;
            float v0 = nv4.x*r_ + h4.x, v1 = nv4.y*r_ + h4.y;
            float v2 = nv4.z*r_ + h4.z, v3 = nv4.w*r_ + h4.w;
            float s  = v0+v1+v2+v3;
            float s2 = v0*v0+v1*v1+v2*v2+v3*v3;
            #pragma unroll
            for (int o = 16; o; o >>= 1) {
                s  += __shfl_xor_sync(0xffffffffu, s,  o);
                s2 += __shfl_xor_sync(0xffffffffu, s2, o);
            }
            float mu  = s * (1.0f/128.0f);
            float var = s2 * (1.0f/128.0f) - mu*mu;
            float is  = rsqrtf(var + 1e-5f);
            if (n < NN) {
                float4 g4 = *(const float4*)&ln_g[layer*CC + lane*4];
                float4 b4 = *(const float4*)&ln_b[layer*CC + lane*4];
                float4 o4;
                o4.x = (v0-mu)*is*g4.x + b4.x;
                o4.y = (v1-mu)*is*g4.y + b4.y;
                o4.z = (v2-mu)*is*g4.z + b4.z;
                o4.w = (v3-mu)*is*g4.w + b4.w;
                *(float4*)&g_h[idx] = o4;
            }
        }
    }
}

// ---------------- regression head ----------------
__global__ void k_reg(const float* __restrict__ reg_w,
                      const float* __restrict__ reg_b,
                      float* __restrict__ out)
{
    int b = blockIdx.y, t = threadIdx.x;
    __shared__ float rw[PP*2*CC];
    __shared__ float st[128*33];
    for (int i = t; i < PP*2*CC; i += 128) rw[i] = reg_w[i];
    int nbase = blockIdx.x*128;
    float acc[PP];
    #pragma unroll
    for (int p = 0; p < PP; p++) acc[p] = 0.f;
    for (int src = 0; src < 2; src++) {
        const float* S = src ? g_h : g_skip;
        for (int c0 = 0; c0 < CC; c0 += 32) {
            __syncthreads();
            #pragma unroll
            for (int k = 0; k < 32; k++) {
                int lin = t + k*128;
                int rr = lin >> 5, cc = lin & 31;
                int n = nbase + rr;
                st[rr*33+cc] = (n < NN) ? S[((size_t)(b*NN) + n)*CC + c0 + cc] : 0.f;
            }
            __syncthreads();
            #pragma unroll
            for (int cc = 0; cc < 32; cc++) {
                float v = st[t*33+cc];
                #pragma unroll
                for (int p = 0; p < PP; p++)
                    acc[p] += v * rw[p*(2*CC) + src*CC + c0 + cc];
            }
        }
    }
    int n = nbase + t;
    if (n < NN) {
        #pragma unroll
        for (int p = 0; p < PP; p++)
            out[((size_t)(b*PP) + p)*NN + n] = acc[p] + reg_b[p];
    }
}

// ---------------- launcher ----------------
extern "C" void kernel_launch(void* const* d_in, const int* in_sizes, int n_in,
                              void* d_out, int out_size)
{
    const float* x        = (const float*)d_in[0];
    const float* xmark    = (const float*)d_in[1];
    const float* node_emb = (const float*)d_in[2];
    const float* time_tab = (const float*)d_in[3];
    const float* week_tab = (const float*)d_in[4];
    const float* input_w  = (const float*)d_in[5];
    const float* input_b  = (const float*)d_in[6];
    const float* w1_w     = (const float*)d_in[7];
    const float* w1_b     = (const float*)d_in[8];
    const float* w2_w     = (const float*)d_in[9];
    const float* w2_b     = (const float*)d_in[10];
    const float* in_w     = (const float*)d_in[11];
    const float* in_b     = (const float*)d_in[12];
    const float* out_w    = (const float*)d_in[13];
    const float* out_b    = (const float*)d_in[14];
    const float* ln_g     = (const float*)d_in[15];
    const float* ln_b     = (const float*)d_in[16];
    const float* reg_w    = (const float*)d_in[17];
    const float* reg_b    = (const float*)d_in[18];
    const float* proj     = (const float*)d_in[19];
    float* out = (float*)d_out;

    cudaFuncSetAttribute(k_num,    cudaFuncAttributeMaxDynamicSharedMemorySize, SMEM_NUM);
    cudaFuncSetAttribute(k_gatekv, cudaFuncAttributeMaxDynamicSharedMemorySize, SMEM_GATE);

    dim3 gBN(NBLK, BB);

    k_wprep<<<LL, 256>>>(in_w, out_w);
    k_const<<<BB, 128>>>(xmark, time_tab, week_tab, input_w, input_b,
                         w1_w, w1_b, w2_w, w2_b, proj);
    k_node<<<(NN + 255)/256, 256>>>(node_emb, w1_w, w2_w);
    k_colmax_part<<<NCH, 256>>>(proj);
    k_stab<<<BB, 64>>>();
    k_phi<<<gBN, 128>>>(proj);
    k_input<<<gBN, 128>>>(x, input_w, node_emb);
    k_ksum<<<dim3(NCH, BB), 256>>>();
    k_ksumred<<<BB, 64>>>();
    k_den<<<gBN, 128>>>();

    for (int l = 0; l < LL; l++) {
        k_gatekv<<<gBN, 512, SMEM_GATE>>>(in_b, out_b, l);
        k_kvred<<<dim3(32, BB), 256>>>();
        k_num<<<gBN, 256, SMEM_NUM>>>(ln_g, ln_b, l);
    }
    k_reg<<<gBN, 128>>>(reg_w, reg_b, out);
}